// round 7
// baseline (speedup 1.0000x reference)
#include <cuda_runtime.h>
#include <cstdint>

// Problem constants
#define BATCH   2
#define SEQ     2048
#define DMODEL  2048
#define NHEADS  16
#define DHEAD   128

#define NCH 64                     // K chunks of 32 (K = 2048)

// ---------------------------------------------------------------------------
// Scratch (alloc-free: __device__ globals)
// ---------------------------------------------------------------------------
__device__ float g_Q[(size_t)BATCH * NHEADS * SEQ * DHEAD];
__device__ float g_K[(size_t)BATCH * NHEADS * SEQ * DHEAD];
__device__ float g_V[(size_t)BATCH * NHEADS * SEQ * DHEAD];
__device__ float g_O[(size_t)BATCH * SEQ * DMODEL];

// tf32 pre-converted fragment-layout operands
__device__ __align__(128) uint32_t g_xf [(size_t)32 * NCH * 4096];   // x      [4096,2048]
__device__ __align__(128) uint32_t g_of [(size_t)32 * NCH * 4096];   // g_O    [4096,2048]
__device__ __align__(128) uint32_t g_wqf[(size_t)48 * NCH * 4096];   // W_qkv  [6144,2048]
__device__ __align__(128) uint32_t g_wof[(size_t)16 * NCH * 4096];   // W_out  [2048,2048]

__device__ __forceinline__ uint32_t f2tf(float x) {
    uint32_t r;
    asm("cvt.rna.tf32.f32 %0, %1;" : "=r"(r) : "f"(x));
    return r;
}

__device__ __forceinline__ void mma_tf32(float* d, const uint32_t* a, const uint32_t* b) {
    asm volatile(
        "mma.sync.aligned.m16n8k8.row.col.f32.tf32.tf32.f32 "
        "{%0,%1,%2,%3}, {%4,%5,%6,%7}, {%8,%9}, {%0,%1,%2,%3};"
        : "+f"(d[0]), "+f"(d[1]), "+f"(d[2]), "+f"(d[3])
        : "r"(a[0]), "r"(a[1]), "r"(a[2]), "r"(a[3]), "r"(b[0]), "r"(b[1]));
}

__device__ __forceinline__ void cpa16(uint32_t dst, const void* src) {
    asm volatile("cp.async.cg.shared.global [%0], [%1], 16;"
                 :: "r"(dst), "l"(src) : "memory");
}
#define CPA_COMMIT() asm volatile("cp.async.commit_group;" ::: "memory")
#define CPA_WAIT(n)  asm volatile("cp.async.wait_group %0;" :: "n"(n) : "memory")

__device__ __forceinline__ uint32_t smem_u32(const void* p) {
    uint32_t a;
    asm("{ .reg .u64 t; cvta.to.shared.u64 t, %1; cvt.u32.u64 %0, t; }"
        : "=r"(a) : "l"(p));
    return a;
}

// Fast exp2 on FMA/ALU pipes only (no MUFU). x must be <= 0 (clamped below).
// Magic-constant integer split + degree-5 Taylor for 2^f, f in [-0.5, 0.5].
// Max rel err ~2.4e-6 (far below the tf32 noise floor of ~5e-4).
__device__ __forceinline__ float fexp2(float x) {
    x = fmaxf(x, -125.0f);
    const float magic = 12582912.0f;           // 1.5 * 2^23
    float z = x + magic;                        // RN -> n = round(x) in low mantissa
    int   i = __float_as_int(z);
    float f = x - (z - magic);                  // f = x - n, in [-0.5, 0.5]
    float p = 1.3333558e-3f;                    // ln2^5/120
    p = fmaf(p, f, 9.6181291e-3f);              // ln2^4/24
    p = fmaf(p, f, 5.5504109e-2f);              // ln2^3/6
    p = fmaf(p, f, 2.4022651e-1f);              // ln2^2/2
    p = fmaf(p, f, 6.9314718e-1f);              // ln2
    p = fmaf(p, f, 1.0f);
    return __int_as_float(__float_as_int(p) + (i << 23));
}

// ---------------------------------------------------------------------------
// Conversion kernels: fp32 row-major -> tf32 fragment layout
// ---------------------------------------------------------------------------
__global__ void __launch_bounds__(256)
conv_A(const float* __restrict__ src, uint32_t* __restrict__ dst)
{
    __shared__ float s[128][33];
    const int ch = blockIdx.x, mb = blockIdx.y, tid = threadIdx.x;
    const float* base = src + (size_t)mb * 128 * DMODEL + ch * 32;
#pragma unroll
    for (int i = 0; i < 4; i++) {
        const int idx = tid + i * 256;
        const int row = idx >> 3, c4 = idx & 7;
        float4 v = *(const float4*)(base + (size_t)row * DMODEL + c4 * 4);
        s[row][c4 * 4 + 0] = v.x; s[row][c4 * 4 + 1] = v.y;
        s[row][c4 * 4 + 2] = v.z; s[row][c4 * 4 + 3] = v.w;
    }
    __syncthreads();
    uint32_t* out = dst + ((size_t)mb * NCH + ch) * 4096;
#pragma unroll
    for (int i = 0; i < 4; i++) {
        const int u = tid + i * 256;
        const int blk = u >> 5, lane = u & 31;
        const int gm = blk >> 2, ks = blk & 3;
        const int r = lane >> 2, kl = lane & 3;
        uint4 w = make_uint4(
            f2tf(s[gm * 16 + r    ][ks * 8 + kl    ]),
            f2tf(s[gm * 16 + r + 8][ks * 8 + kl    ]),
            f2tf(s[gm * 16 + r    ][ks * 8 + kl + 4]),
            f2tf(s[gm * 16 + r + 8][ks * 8 + kl + 4]));
        *(uint4*)(out + (size_t)u * 4) = w;
    }
}

__global__ void __launch_bounds__(256)
conv_B(const float* __restrict__ src, uint32_t* __restrict__ dst)
{
    __shared__ float s[128][33];
    const int ch = blockIdx.x, nb = blockIdx.y, tid = threadIdx.x;
    const float* base = src + (size_t)nb * 128 * DMODEL + ch * 32;
#pragma unroll
    for (int i = 0; i < 4; i++) {
        const int idx = tid + i * 256;
        const int row = idx >> 3, c4 = idx & 7;
        float4 v = *(const float4*)(base + (size_t)row * DMODEL + c4 * 4);
        s[row][c4 * 4 + 0] = v.x; s[row][c4 * 4 + 1] = v.y;
        s[row][c4 * 4 + 2] = v.z; s[row][c4 * 4 + 3] = v.w;
    }
    __syncthreads();
    uint32_t* out = dst + ((size_t)nb * NCH + ch) * 4096;
#pragma unroll
    for (int i = 0; i < 8; i++) {
        const int u = tid + i * 256;
        const int blk = u >> 5, lane = u & 31;
        const int gn = blk >> 2, ks = blk & 3;
        const int n8 = lane >> 2, kl = lane & 3;
        uint2 w = make_uint2(
            f2tf(s[gn * 8 + n8][ks * 8 + kl    ]),
            f2tf(s[gn * 8 + n8][ks * 8 + kl + 4]));
        *(uint2*)(out + (size_t)u * 2) = w;
    }
}

// ---------------------------------------------------------------------------
// Fragment-fed tf32 GEMM (unchanged from round 6)
// ---------------------------------------------------------------------------
#define STAGE_U32 12288
#define GF_SMEM   (4 * STAGE_U32 * 4)    // 196608 bytes

template <int MODE>
__global__ void __launch_bounds__(256)
gemm_f(const uint32_t* __restrict__ Af, const uint32_t* __restrict__ Bf,
       float* __restrict__ C)
{
    extern __shared__ uint32_t us[];
    const int tid = threadIdx.x;
    const int wid = tid >> 5;
    const int lid = tid & 31;
    const int wm  = wid & 1;
    const int wn  = wid >> 1;
    const int mb  = blockIdx.y;
    const int nbx = blockIdx.x;
    const uint32_t sb = smem_u32(us);

    float acc[4][8][4];
#pragma unroll
    for (int i = 0; i < 4; i++)
#pragma unroll
        for (int j = 0; j < 8; j++)
#pragma unroll
            for (int v = 0; v < 4; v++) acc[i][j][v] = 0.0f;

    auto issue = [&](int c, int st) {
        const uint32_t sA = sb + st * (STAGE_U32 * 4);
        const uint32_t sB = sA + 16384;
        const uint32_t* gA  = Af + ((size_t)mb * NCH + c) * 4096;
        const uint32_t* gB0 = Bf + ((size_t)(2 * nbx)     * NCH + c) * 4096;
        const uint32_t* gB1 = Bf + ((size_t)(2 * nbx + 1) * NCH + c) * 4096;
#pragma unroll
        for (int i = 0; i < 4; i++) {
            const int o = tid + i * 256;
            cpa16(sA + o * 16, gA + (size_t)o * 4);
        }
#pragma unroll
        for (int i = 0; i < 4; i++) {
            const int o = tid + i * 256;
            cpa16(sB + o * 16, gB0 + (size_t)o * 4);
        }
#pragma unroll
        for (int i = 0; i < 4; i++) {
            const int o = tid + i * 256;
            cpa16(sB + 16384 + o * 16, gB1 + (size_t)o * 4);
        }
        CPA_COMMIT();
    };

    issue(0, 0);
    issue(1, 1);

    for (int c = 0; c < NCH; ++c) {
        const int st = c & 3;
        if (c + 2 < NCH)      { issue(c + 2, (c + 2) & 3); CPA_WAIT(2); }
        else if (c + 1 < NCH) { CPA_WAIT(1); }
        else                  { CPA_WAIT(0); }
        __syncthreads();

        const uint32_t* uA = us + st * STAGE_U32;
        const uint32_t* uB = uA + 4096;
#pragma unroll
        for (int ks = 0; ks < 4; ks++) {
            uint32_t a[4][4], b[8][2];
#pragma unroll
            for (int mt = 0; mt < 4; mt++)
                *(uint4*)a[mt] = *(const uint4*)&uA[(((wm * 4 + mt) * 4 + ks) * 32 + lid) * 4];
#pragma unroll
            for (int nt = 0; nt < 8; nt++) {
                const int gn = wn * 8 + nt;
                *(uint2*)b[nt] = *(const uint2*)
                    &uB[((gn >> 4) * 4096) + (((gn & 15) * 4 + ks) * 32 + lid) * 2];
            }
#pragma unroll
            for (int mt = 0; mt < 4; mt++)
#pragma unroll
                for (int nt = 0; nt < 8; nt++)
                    mma_tf32(acc[mt][nt], a[mt], b[nt]);
        }
    }

    const int lr  = lid >> 2;
    const int lc2 = (lid & 3) * 2;
    const int m0  = mb * 128;
    const int n0  = nbx * 256;
#pragma unroll
    for (int mt = 0; mt < 4; mt++) {
        const int m = m0 + wm * 64 + mt * 16 + lr;
#pragma unroll
        for (int nt = 0; nt < 8; nt++) {
            const int cg = n0 + wn * 64 + nt * 8 + lc2;
            if (MODE == 0) {
                float* dst = C + (size_t)m * DMODEL + cg;
                *(float2*)dst                         = make_float2(acc[mt][nt][0], acc[mt][nt][1]);
                *(float2*)(dst + (size_t)8 * DMODEL)  = make_float2(acc[mt][nt][2], acc[mt][nt][3]);
            } else {
                const int t = cg >> 11;
                const int h = (cg >> 7) & (NHEADS - 1);
                const int d = cg & (DHEAD - 1);
                const int b = m >> 11;
                const int s = m & (SEQ - 1);
                float* basep = (t == 0 ? g_Q : (t == 1 ? g_K : g_V));
                float* dst = basep + ((size_t)(b * NHEADS + h) * SEQ + s) * DHEAD + d;
                *(float2*)dst                = make_float2(acc[mt][nt][0], acc[mt][nt][1]);
                *(float2*)(dst + 8 * DHEAD)  = make_float2(acc[mt][nt][2], acc[mt][nt][3]);
            }
        }
    }
}

// ---------------------------------------------------------------------------
// Flash attention on tensor cores, causal. Softmax in log2 domain with
// FMA-pipe fexp2 (no MUFU). Otherwise identical to round 6.
// ---------------------------------------------------------------------------
#define ABR 128
#define ABC 64

#define AQ_OFF   0
#define AQ_BYTES (128 * 132 * 4)
#define AK_OFF   (AQ_OFF + AQ_BYTES)
#define AK_BYTES (128 * 66 * 4)
#define AV_OFF   (AK_OFF + AK_BYTES)
#define AV_BYTES (128 * 66 * 4)
#define AP_OFF   (AV_OFF + AV_BYTES)
#define AP_BYTES (8 * 16 * 68 * 4)
#define ATT2_SMEM (AP_OFF + AP_BYTES)

__global__ void __launch_bounds__(256, 1)
flash_attn_mma()
{
    extern __shared__ char sm[];
    uint32_t* QA = (uint32_t*)(sm + AQ_OFF);
    uint32_t* KB = (uint32_t*)(sm + AK_OFF);
    uint32_t* VB = (uint32_t*)(sm + AV_OFF);

    const int tid = threadIdx.x;
    const int wid = tid >> 5;
    const int lid = tid & 31;
    const int qb  = gridDim.x - 1 - blockIdx.x;
    const int bh  = blockIdx.y;
    const int q0  = qb * ABR;
    const int b   = bh >> 4;
    const int h   = bh & (NHEADS - 1);

    const float* Qg = g_Q + (size_t)bh * SEQ * DHEAD;
    const float* Kg = g_K + (size_t)bh * SEQ * DHEAD;
    const float* Vg = g_V + (size_t)bh * SEQ * DHEAD;

#pragma unroll
    for (int it = 0; it < 16; it++) {
        const int idx = tid + it * 256;
        const int d4  = idx >> 7;
        const int r   = idx & 127;
        float4 v = *(const float4*)(Qg + (size_t)(q0 + r) * DHEAD + d4 * 4);
        const int w    = r >> 4;
        const int kt   = d4 >> 1;
        const int slot = ((d4 & 1) ? 2 : 0) + ((r >> 3) & 1);
        uint32_t* p = &QA[(kt * 8 + w) * 132 + ((r & 7) * 4) * 4 + slot];
        p[0]  = f2tf(v.x);
        p[4]  = f2tf(v.y);
        p[8]  = f2tf(v.z);
        p[12] = f2tf(v.w);
    }

    const int lr = lid >> 2;
    const int lc = lid & 3;
    uint32_t* Pw = (uint32_t*)(sm + AP_OFF) + wid * (16 * 68);

    float o[16][4];
#pragma unroll
    for (int nt = 0; nt < 16; nt++)
#pragma unroll
        for (int v = 0; v < 4; v++) o[nt][v] = 0.0f;

    float m0 = -1e30f, m1 = -1e30f, l0 = 0.0f, l1 = 0.0f;
    // scale in log2 domain: (1/sqrt(128)) * log2(e)
    const float scale2 = 0.08838834764831845f * 1.4426950408889634f;
    const int row0 = q0 + wid * 16 + lr;
    const int row1 = row0 + 8;

    const int nkb = 2 * qb + 2;
    for (int kb = 0; kb < nkb; kb++) {
        const int k0 = kb * ABC;
        __syncthreads();

#pragma unroll
        for (int it = 0; it < 8; it++) {
            const int idx = tid + it * 256;
            const int d4  = idx >> 6;
            const int s   = idx & 63;
            float4 kv = *(const float4*)(Kg + (size_t)(k0 + s) * DHEAD + d4 * 4);
            {
                const int blockid = (d4 >> 1) * 8 + (s >> 3);
                const int slot = (d4 & 1);
                uint32_t* p = &KB[blockid * 66 + ((s & 7) * 4) * 2 + slot];
                p[0] = f2tf(kv.x);
                p[2] = f2tf(kv.y);
                p[4] = f2tf(kv.z);
                p[6] = f2tf(kv.w);
            }
            float4 vv = *(const float4*)(Vg + (size_t)(k0 + s) * DHEAD + d4 * 4);
            {
                const int blockid = (d4 >> 1) * 8 + (s >> 3);
                const int slot = ((s & 7) < 4) ? 0 : 1;
                const int lane0 = (d4 & 1) * 16 + (s & 3);
                uint32_t* p = &VB[blockid * 66 + lane0 * 2 + slot];
                p[0]  = f2tf(vv.x);
                p[8]  = f2tf(vv.y);
                p[16] = f2tf(vv.z);
                p[24] = f2tf(vv.w);
            }
        }
        __syncthreads();

        float s[8][4];
#pragma unroll
        for (int nt = 0; nt < 8; nt++)
#pragma unroll
            for (int v = 0; v < 4; v++) s[nt][v] = 0.0f;

#pragma unroll
        for (int kt = 0; kt < 16; kt++) {
            uint32_t a[4];
            *(uint4*)a = *(const uint4*)&QA[(kt * 8 + wid) * 132 + lid * 4];
#pragma unroll
            for (int nt = 0; nt < 8; nt++) {
                uint32_t bf[2];
                *(uint2*)bf = *(const uint2*)&KB[(kt * 8 + nt) * 66 + lid * 2];
                mma_tf32(s[nt], a, bf);
            }
        }

        const bool domask = (kb >= 2 * qb);
        float ml0 = -1e30f, ml1 = -1e30f;
#pragma unroll
        for (int nt = 0; nt < 8; nt++) {
            const int c0 = k0 + nt * 8 + lc * 2;
            s[nt][0] *= scale2; s[nt][1] *= scale2;
            s[nt][2] *= scale2; s[nt][3] *= scale2;
            if (domask) {
                if (c0     > row0) s[nt][0] = -1e30f;
                if (c0 + 1 > row0) s[nt][1] = -1e30f;
                if (c0     > row1) s[nt][2] = -1e30f;
                if (c0 + 1 > row1) s[nt][3] = -1e30f;
            }
            ml0 = fmaxf(ml0, fmaxf(s[nt][0], s[nt][1]));
            ml1 = fmaxf(ml1, fmaxf(s[nt][2], s[nt][3]));
        }
        ml0 = fmaxf(ml0, __shfl_xor_sync(0xffffffffu, ml0, 1));
        ml0 = fmaxf(ml0, __shfl_xor_sync(0xffffffffu, ml0, 2));
        ml1 = fmaxf(ml1, __shfl_xor_sync(0xffffffffu, ml1, 1));
        ml1 = fmaxf(ml1, __shfl_xor_sync(0xffffffffu, ml1, 2));

        const float mn0 = fmaxf(m0, ml0);
        const float mn1 = fmaxf(m1, ml1);
        const float f0 = fexp2(m0 - mn0);
        const float f1 = fexp2(m1 - mn1);
        m0 = mn0; m1 = mn1;

        float rs0 = 0.0f, rs1 = 0.0f;
#pragma unroll
        for (int nt = 0; nt < 8; nt++) {
            s[nt][0] = fexp2(s[nt][0] - mn0);
            s[nt][1] = fexp2(s[nt][1] - mn0);
            s[nt][2] = fexp2(s[nt][2] - mn1);
            s[nt][3] = fexp2(s[nt][3] - mn1);
            rs0 += s[nt][0] + s[nt][1];
            rs1 += s[nt][2] + s[nt][3];
        }
        rs0 += __shfl_xor_sync(0xffffffffu, rs0, 1);
        rs0 += __shfl_xor_sync(0xffffffffu, rs0, 2);
        rs1 += __shfl_xor_sync(0xffffffffu, rs1, 1);
        rs1 += __shfl_xor_sync(0xffffffffu, rs1, 2);
        l0 = l0 * f0 + rs0;
        l1 = l1 * f1 + rs1;

#pragma unroll
        for (int nt = 0; nt < 16; nt++) {
            o[nt][0] *= f0; o[nt][1] *= f0;
            o[nt][2] *= f1; o[nt][3] *= f1;
        }

#pragma unroll
        for (int nt = 0; nt < 8; nt++) {
            *(uint2*)&Pw[lr * 68 + nt * 8 + lc * 2] =
                make_uint2(f2tf(s[nt][0]), f2tf(s[nt][1]));
            *(uint2*)&Pw[(lr + 8) * 68 + nt * 8 + lc * 2] =
                make_uint2(f2tf(s[nt][2]), f2tf(s[nt][3]));
        }
        __syncwarp();

#pragma unroll
        for (int ks = 0; ks < 8; ks++) {
            uint32_t a[4];
            a[0] = Pw[lr * 68 + ks * 8 + lc];
            a[1] = Pw[(lr + 8) * 68 + ks * 8 + lc];
            a[2] = Pw[lr * 68 + ks * 8 + lc + 4];
            a[3] = Pw[(lr + 8) * 68 + ks * 8 + lc + 4];
#pragma unroll
            for (int nt = 0; nt < 16; nt++) {
                uint32_t bf[2];
                *(uint2*)bf = *(const uint2*)&VB[(nt * 8 + ks) * 66 + lid * 2];
                mma_tf32(o[nt], a, bf);
            }
        }
    }

    const float inv0 = 1.0f / l0;
    const float inv1 = 1.0f / l1;
    float* O0 = g_O + (((size_t)b * SEQ + row0) * NHEADS + h) * DHEAD;
    float* O1 = g_O + (((size_t)b * SEQ + row1) * NHEADS + h) * DHEAD;
#pragma unroll
    for (int nt = 0; nt < 16; nt++) {
        const int col = nt * 8 + lc * 2;
        *(float2*)(O0 + col) = make_float2(o[nt][0] * inv0, o[nt][1] * inv0);
        *(float2*)(O1 + col) = make_float2(o[nt][2] * inv1, o[nt][3] * inv1);
    }
}

// ---------------------------------------------------------------------------
// Launch
// ---------------------------------------------------------------------------
extern "C" void kernel_launch(void* const* d_in, const int* in_sizes, int n_in,
                              void* d_out, int out_size)
{
    const float* x    = (const float*)d_in[0];
    const float* Wqkv = (const float*)d_in[1];
    const float* Wout = (const float*)d_in[2];
    float* out = (float*)d_out;

    cudaFuncSetAttribute(gemm_f<1>, cudaFuncAttributeMaxDynamicSharedMemorySize, GF_SMEM);
    cudaFuncSetAttribute(gemm_f<0>, cudaFuncAttributeMaxDynamicSharedMemorySize, GF_SMEM);
    cudaFuncSetAttribute(flash_attn_mma, cudaFuncAttributeMaxDynamicSharedMemorySize, ATT2_SMEM);

    uint32_t *xf, *of, *wqf, *wof;
    cudaGetSymbolAddress((void**)&xf,  g_xf);
    cudaGetSymbolAddress((void**)&of,  g_of);
    cudaGetSymbolAddress((void**)&wqf, g_wqf);
    cudaGetSymbolAddress((void**)&wof, g_wof);
    float* oPtr = nullptr;
    cudaGetSymbolAddress((void**)&oPtr, g_O);

    // Pre-convert operands into tf32 fragment layouts
    conv_A<<<dim3(NCH, 32), 256>>>(x,    xf);
    conv_B<<<dim3(NCH, 48), 256>>>(Wqkv, wqf);
    conv_B<<<dim3(NCH, 16), 256>>>(Wout, wof);

    // Stage 1: QKV projection (fragment-fed tensor cores, scatter epilogue)
    gemm_f<1><<<dim3(24, 32), 256, GF_SMEM>>>(xf, wqf, nullptr);

    // Stage 2: flash attention (tensor cores, MUFU-free softmax)
    flash_attn_mma<<<dim3(SEQ / ABR, BATCH * NHEADS), 256, ATT2_SMEM>>>();

    // Stage 3: convert attention output, then output projection
    conv_A<<<dim3(NCH, 32), 256>>>(oPtr, of);
    gemm_f<0><<<dim3(8, 32), 256, GF_SMEM>>>(of, wof, out);
}

// round 8
// speedup vs baseline: 1.2796x; 1.2796x over previous
#include <cuda_runtime.h>
#include <cstdint>

// Problem constants
#define BATCH   2
#define SEQ     2048
#define DMODEL  2048
#define NHEADS  16
#define DHEAD   128

#define NCH 64                     // K chunks of 32 (K = 2048)

// ---------------------------------------------------------------------------
// Scratch (alloc-free: __device__ globals)
// ---------------------------------------------------------------------------
__device__ float g_O[(size_t)BATCH * SEQ * DMODEL];

// tf32 pre-converted fragment-layout GEMM operands
__device__ __align__(128) uint32_t g_xf [(size_t)32 * NCH * 4096];   // x      [4096,2048]
__device__ __align__(128) uint32_t g_of [(size_t)32 * NCH * 4096];   // g_O    [4096,2048]
__device__ __align__(128) uint32_t g_wqf[(size_t)48 * NCH * 4096];   // W_qkv  [6144,2048]
__device__ __align__(128) uint32_t g_wof[(size_t)16 * NCH * 4096];   // W_out  [2048,2048]

// tf32 fragment-layout Q/K/V produced by the QKV GEMM epilogue
// Qf: [bh][s>>7][128 blocks (kt*8+w16)][32 lanes][4 slots], block stride 128 u32
// Kf: [bh][s>>6][128 blocks (kt*8+ks)][lane*2+slot], block stride 72 u32 (padded)
// Vf: [bh][s>>6][128 blocks (nt*8+ks)][lane*2+slot], block stride 72 u32
__device__ __align__(128) uint32_t g_Qf[(size_t)32 * 16 * 128 * 128];
__device__ __align__(128) uint32_t g_Kf[(size_t)32 * 32 * 128 * 72];
__device__ __align__(128) uint32_t g_Vf[(size_t)32 * 32 * 128 * 72];

__device__ __forceinline__ uint32_t f2tf(float x) {
    uint32_t r;
    asm("cvt.rna.tf32.f32 %0, %1;" : "=r"(r) : "f"(x));
    return r;
}

__device__ __forceinline__ void mma_tf32(float* d, const uint32_t* a, const uint32_t* b) {
    asm volatile(
        "mma.sync.aligned.m16n8k8.row.col.f32.tf32.tf32.f32 "
        "{%0,%1,%2,%3}, {%4,%5,%6,%7}, {%8,%9}, {%0,%1,%2,%3};"
        : "+f"(d[0]), "+f"(d[1]), "+f"(d[2]), "+f"(d[3])
        : "r"(a[0]), "r"(a[1]), "r"(a[2]), "r"(a[3]), "r"(b[0]), "r"(b[1]));
}

__device__ __forceinline__ void cpa16(uint32_t dst, const void* src) {
    asm volatile("cp.async.cg.shared.global [%0], [%1], 16;"
                 :: "r"(dst), "l"(src) : "memory");
}
#define CPA_COMMIT() asm volatile("cp.async.commit_group;" ::: "memory")
#define CPA_WAIT(n)  asm volatile("cp.async.wait_group %0;" :: "n"(n) : "memory")

__device__ __forceinline__ uint32_t smem_u32(const void* p) {
    uint32_t a;
    asm("{ .reg .u64 t; cvta.to.shared.u64 t, %1; cvt.u32.u64 %0, t; }"
        : "=r"(a) : "l"(p));
    return a;
}

// Fragment-layout index helpers (element (s,d) of head-batch bh)
__device__ __forceinline__ size_t qf_idx(int bh, int s, int d) {
    return (size_t)((bh * 16 + (s >> 7)) * 128 + (d >> 3) * 8 + ((s >> 4) & 7)) * 128
         + (((s & 7) * 4 + (d & 3)) << 2) + (((d >> 2) & 1) << 1) + ((s >> 3) & 1);
}
__device__ __forceinline__ size_t kf_idx(int bh, int s, int d) {
    return (size_t)((bh * 32 + (s >> 6)) * 128 + (d >> 3) * 8 + ((s >> 3) & 7)) * 72
         + (((s & 7) * 4 + (d & 3)) << 1) + ((d >> 2) & 1);
}
__device__ __forceinline__ size_t vf_idx(int bh, int s, int d) {
    return (size_t)((bh * 32 + (s >> 6)) * 128 + (d >> 3) * 8 + ((s >> 3) & 7)) * 72
         + (((d & 7) * 4 + (s & 3)) << 1) + ((s >> 2) & 1);
}

// ---------------------------------------------------------------------------
// Conversion kernels: fp32 row-major -> tf32 fragment layout
// ---------------------------------------------------------------------------
__global__ void __launch_bounds__(256)
conv_A(const float* __restrict__ src, uint32_t* __restrict__ dst)
{
    __shared__ float s[128][33];
    const int ch = blockIdx.x, mb = blockIdx.y, tid = threadIdx.x;
    const float* base = src + (size_t)mb * 128 * DMODEL + ch * 32;
#pragma unroll
    for (int i = 0; i < 4; i++) {
        const int idx = tid + i * 256;
        const int row = idx >> 3, c4 = idx & 7;
        float4 v = *(const float4*)(base + (size_t)row * DMODEL + c4 * 4);
        s[row][c4 * 4 + 0] = v.x; s[row][c4 * 4 + 1] = v.y;
        s[row][c4 * 4 + 2] = v.z; s[row][c4 * 4 + 3] = v.w;
    }
    __syncthreads();
    uint32_t* out = dst + ((size_t)mb * NCH + ch) * 4096;
#pragma unroll
    for (int i = 0; i < 4; i++) {
        const int u = tid + i * 256;
        const int blk = u >> 5, lane = u & 31;
        const int gm = blk >> 2, ks = blk & 3;
        const int r = lane >> 2, kl = lane & 3;
        uint4 w = make_uint4(
            f2tf(s[gm * 16 + r    ][ks * 8 + kl    ]),
            f2tf(s[gm * 16 + r + 8][ks * 8 + kl    ]),
            f2tf(s[gm * 16 + r    ][ks * 8 + kl + 4]),
            f2tf(s[gm * 16 + r + 8][ks * 8 + kl + 4]));
        *(uint4*)(out + (size_t)u * 4) = w;
    }
}

__global__ void __launch_bounds__(256)
conv_B(const float* __restrict__ src, uint32_t* __restrict__ dst)
{
    __shared__ float s[128][33];
    const int ch = blockIdx.x, nb = blockIdx.y, tid = threadIdx.x;
    const float* base = src + (size_t)nb * 128 * DMODEL + ch * 32;
#pragma unroll
    for (int i = 0; i < 4; i++) {
        const int idx = tid + i * 256;
        const int row = idx >> 3, c4 = idx & 7;
        float4 v = *(const float4*)(base + (size_t)row * DMODEL + c4 * 4);
        s[row][c4 * 4 + 0] = v.x; s[row][c4 * 4 + 1] = v.y;
        s[row][c4 * 4 + 2] = v.z; s[row][c4 * 4 + 3] = v.w;
    }
    __syncthreads();
    uint32_t* out = dst + ((size_t)nb * NCH + ch) * 4096;
#pragma unroll
    for (int i = 0; i < 8; i++) {
        const int u = tid + i * 256;
        const int blk = u >> 5, lane = u & 31;
        const int gn = blk >> 2, ks = blk & 3;
        const int n8 = lane >> 2, kl = lane & 3;
        uint2 w = make_uint2(
            f2tf(s[gn * 8 + n8][ks * 8 + kl    ]),
            f2tf(s[gn * 8 + n8][ks * 8 + kl + 4]));
        *(uint2*)(out + (size_t)u * 2) = w;
    }
}

// ---------------------------------------------------------------------------
// Fragment-fed tf32 GEMM (4-stage ring, as round 6).
// MODE 0: C row-major [M, 2048].
// MODE 1: QKV — epilogue writes Q/K/V in tf32 FRAGMENT layouts.
// ---------------------------------------------------------------------------
#define STAGE_U32 12288
#define GF_SMEM   (4 * STAGE_U32 * 4)    // 196608 bytes

template <int MODE>
__global__ void __launch_bounds__(256)
gemm_f(const uint32_t* __restrict__ Af, const uint32_t* __restrict__ Bf,
       float* __restrict__ C)
{
    extern __shared__ uint32_t us[];
    const int tid = threadIdx.x;
    const int wid = tid >> 5;
    const int lid = tid & 31;
    const int wm  = wid & 1;
    const int wn  = wid >> 1;
    const int mb  = blockIdx.y;
    const int nbx = blockIdx.x;
    const uint32_t sb = smem_u32(us);

    float acc[4][8][4];
#pragma unroll
    for (int i = 0; i < 4; i++)
#pragma unroll
        for (int j = 0; j < 8; j++)
#pragma unroll
            for (int v = 0; v < 4; v++) acc[i][j][v] = 0.0f;

    auto issue = [&](int c, int st) {
        const uint32_t sA = sb + st * (STAGE_U32 * 4);
        const uint32_t sB = sA + 16384;
        const uint32_t* gA  = Af + ((size_t)mb * NCH + c) * 4096;
        const uint32_t* gB0 = Bf + ((size_t)(2 * nbx)     * NCH + c) * 4096;
        const uint32_t* gB1 = Bf + ((size_t)(2 * nbx + 1) * NCH + c) * 4096;
#pragma unroll
        for (int i = 0; i < 4; i++) {
            const int o = tid + i * 256;
            cpa16(sA + o * 16, gA + (size_t)o * 4);
        }
#pragma unroll
        for (int i = 0; i < 4; i++) {
            const int o = tid + i * 256;
            cpa16(sB + o * 16, gB0 + (size_t)o * 4);
        }
#pragma unroll
        for (int i = 0; i < 4; i++) {
            const int o = tid + i * 256;
            cpa16(sB + 16384 + o * 16, gB1 + (size_t)o * 4);
        }
        CPA_COMMIT();
    };

    issue(0, 0);
    issue(1, 1);

    for (int c = 0; c < NCH; ++c) {
        const int st = c & 3;
        if (c + 2 < NCH)      { issue(c + 2, (c + 2) & 3); CPA_WAIT(2); }
        else if (c + 1 < NCH) { CPA_WAIT(1); }
        else                  { CPA_WAIT(0); }
        __syncthreads();

        const uint32_t* uA = us + st * STAGE_U32;
        const uint32_t* uB = uA + 4096;
#pragma unroll
        for (int ks = 0; ks < 4; ks++) {
            uint32_t a[4][4], b[8][2];
#pragma unroll
            for (int mt = 0; mt < 4; mt++)
                *(uint4*)a[mt] = *(const uint4*)&uA[(((wm * 4 + mt) * 4 + ks) * 32 + lid) * 4];
#pragma unroll
            for (int nt = 0; nt < 8; nt++) {
                const int gn = wn * 8 + nt;
                *(uint2*)b[nt] = *(const uint2*)
                    &uB[((gn >> 4) * 4096) + (((gn & 15) * 4 + ks) * 32 + lid) * 2];
            }
#pragma unroll
            for (int mt = 0; mt < 4; mt++)
#pragma unroll
                for (int nt = 0; nt < 8; nt++)
                    mma_tf32(acc[mt][nt], a[mt], b[nt]);
        }
    }

    // ---- epilogue ----
    const int lr  = lid >> 2;
    const int lc2 = (lid & 3) * 2;
    const int m0  = mb * 128;
    const int n0  = nbx * 256;
    const int t   = n0 >> 11;                  // uniform per CTA (0=Q,1=K,2=V for MODE 1)
#pragma unroll
    for (int mt = 0; mt < 4; mt++) {
        const int m = m0 + wm * 64 + mt * 16 + lr;
#pragma unroll
        for (int nt = 0; nt < 8; nt++) {
            const int cg = n0 + wn * 64 + nt * 8 + lc2;
            if (MODE == 0) {
                float* dst = C + (size_t)m * DMODEL + cg;
                *(float2*)dst                         = make_float2(acc[mt][nt][0], acc[mt][nt][1]);
                *(float2*)(dst + (size_t)8 * DMODEL)  = make_float2(acc[mt][nt][2], acc[mt][nt][3]);
            } else {
                const int h  = (cg >> 7) & (NHEADS - 1);
                const int d  = cg & (DHEAD - 1);
                const int b  = m >> 11;
                const int s  = m & (SEQ - 1);
                const int bh = b * NHEADS + h;
                if (t == 0) {
                    g_Qf[qf_idx(bh, s,     d    )] = f2tf(acc[mt][nt][0]);
                    g_Qf[qf_idx(bh, s,     d + 1)] = f2tf(acc[mt][nt][1]);
                    g_Qf[qf_idx(bh, s + 8, d    )] = f2tf(acc[mt][nt][2]);
                    g_Qf[qf_idx(bh, s + 8, d + 1)] = f2tf(acc[mt][nt][3]);
                } else if (t == 1) {
                    g_Kf[kf_idx(bh, s,     d    )] = f2tf(acc[mt][nt][0]);
                    g_Kf[kf_idx(bh, s,     d + 1)] = f2tf(acc[mt][nt][1]);
                    g_Kf[kf_idx(bh, s + 8, d    )] = f2tf(acc[mt][nt][2]);
                    g_Kf[kf_idx(bh, s + 8, d + 1)] = f2tf(acc[mt][nt][3]);
                } else {
                    g_Vf[vf_idx(bh, s,     d    )] = f2tf(acc[mt][nt][0]);
                    g_Vf[vf_idx(bh, s,     d + 1)] = f2tf(acc[mt][nt][1]);
                    g_Vf[vf_idx(bh, s + 8, d    )] = f2tf(acc[mt][nt][2]);
                    g_Vf[vf_idx(bh, s + 8, d + 1)] = f2tf(acc[mt][nt][3]);
                }
            }
        }
    }
}

// ---------------------------------------------------------------------------
// Flash attention v3: 128-thread CTAs (4 warps), 64-row Q tiles.
// Q fragments in registers (LDG once), K/V fragments via cp.async from the
// pre-converted global layouts, 91KB smem -> 2 CTAs/SM for overlap.
// ---------------------------------------------------------------------------
#define KV_BLK_U32 9216                 // 128 blocks * 72 u32
#define ATT3_SMEM  ((2 * KV_BLK_U32 + 4 * 1088) * 4)   // 91136 bytes

__global__ void __launch_bounds__(128)
flash_attn_v3()
{
    extern __shared__ uint32_t sm32[];
    uint32_t* KB = sm32;                        // [9216]
    uint32_t* VB = sm32 + KV_BLK_U32;           // [9216]
    const int tid = threadIdx.x;
    const int wid = tid >> 5;
    const int lid = tid & 31;
    const int qb  = gridDim.x - 1 - blockIdx.x; // big tiles first
    const int bh  = blockIdx.y;
    const int q0  = qb * 64;
    const int b   = bh >> 4;
    const int h   = bh & (NHEADS - 1);
    uint32_t* Pw = sm32 + 2 * KV_BLK_U32 + wid * 1088;   // 16 rows x 68
    const uint32_t sb = smem_u32(sm32);

    // ---- Q fragments into registers (reused every iteration) ----
    uint32_t q[16][4];
    {
        const uint4* qg = (const uint4*)g_Qf;
        const int blk0 = (bh * 16 + (qb >> 1)) * 128 + (qb & 1) * 4 + wid;
#pragma unroll
        for (int kt = 0; kt < 16; kt++) {
            uint4 v = __ldg(&qg[(size_t)(blk0 + kt * 8) * 32 + lid]);
            q[kt][0] = v.x; q[kt][1] = v.y; q[kt][2] = v.z; q[kt][3] = v.w;
        }
    }

    auto issueKV = [&](int kb) {
        const uint4* gk = (const uint4*)(g_Kf + (size_t)(bh * 32 + kb) * KV_BLK_U32);
        const uint4* gv = (const uint4*)(g_Vf + (size_t)(bh * 32 + kb) * KV_BLK_U32);
#pragma unroll
        for (int i = 0; i < 18; i++)
            cpa16(sb + (tid + i * 128) * 16, gk + tid + i * 128);
#pragma unroll
        for (int i = 0; i < 18; i++)
            cpa16(sb + KV_BLK_U32 * 4 + (tid + i * 128) * 16, gv + tid + i * 128);
        CPA_COMMIT();
    };

    float o[16][4];
#pragma unroll
    for (int nt = 0; nt < 16; nt++)
#pragma unroll
        for (int v = 0; v < 4; v++) o[nt][v] = 0.0f;

    float mx0 = -1e30f, mx1 = -1e30f, l0 = 0.0f, l1 = 0.0f;
    const float scale = 0.08838834764831845f;   // 1/sqrt(128)
    const int lr = lid >> 2;
    const int lc = lid & 3;
    const int row0 = q0 + wid * 16 + lr;
    const int row1 = row0 + 8;

    issueKV(0);

    for (int kb = 0; kb <= qb; kb++) {
        CPA_WAIT(0);
        __syncthreads();

        // ---- S = Q . K^T : 16 rows x 64 cols per warp ----
        float s[8][4];
#pragma unroll
        for (int nt = 0; nt < 8; nt++)
#pragma unroll
            for (int v = 0; v < 4; v++) s[nt][v] = 0.0f;

#pragma unroll
        for (int kt = 0; kt < 16; kt++)
#pragma unroll
            for (int nt = 0; nt < 8; nt++) {
                uint32_t bf[2];
                *(uint2*)bf = *(const uint2*)&KB[(kt * 8 + nt) * 72 + lid * 2];
                mma_tf32(s[nt], q[kt], bf);
            }

        // ---- scale + causal mask (diagonal block only) + online softmax ----
        const bool domask = (kb == qb);
        const int k0 = kb * 64;
        float ml0 = -1e30f, ml1 = -1e30f;
#pragma unroll
        for (int nt = 0; nt < 8; nt++) {
            const int c0 = k0 + nt * 8 + lc * 2;
            s[nt][0] *= scale; s[nt][1] *= scale;
            s[nt][2] *= scale; s[nt][3] *= scale;
            if (domask) {
                if (c0     > row0) s[nt][0] = -1e30f;
                if (c0 + 1 > row0) s[nt][1] = -1e30f;
                if (c0     > row1) s[nt][2] = -1e30f;
                if (c0 + 1 > row1) s[nt][3] = -1e30f;
            }
            ml0 = fmaxf(ml0, fmaxf(s[nt][0], s[nt][1]));
            ml1 = fmaxf(ml1, fmaxf(s[nt][2], s[nt][3]));
        }
        ml0 = fmaxf(ml0, __shfl_xor_sync(0xffffffffu, ml0, 1));
        ml0 = fmaxf(ml0, __shfl_xor_sync(0xffffffffu, ml0, 2));
        ml1 = fmaxf(ml1, __shfl_xor_sync(0xffffffffu, ml1, 1));
        ml1 = fmaxf(ml1, __shfl_xor_sync(0xffffffffu, ml1, 2));

        const float mn0 = fmaxf(mx0, ml0);
        const float mn1 = fmaxf(mx1, ml1);
        const float f0 = __expf(mx0 - mn0);
        const float f1 = __expf(mx1 - mn1);
        mx0 = mn0; mx1 = mn1;

        float rs0 = 0.0f, rs1 = 0.0f;
#pragma unroll
        for (int nt = 0; nt < 8; nt++) {
            s[nt][0] = __expf(s[nt][0] - mn0);
            s[nt][1] = __expf(s[nt][1] - mn0);
            s[nt][2] = __expf(s[nt][2] - mn1);
            s[nt][3] = __expf(s[nt][3] - mn1);
            rs0 += s[nt][0] + s[nt][1];
            rs1 += s[nt][2] + s[nt][3];
        }
        rs0 += __shfl_xor_sync(0xffffffffu, rs0, 1);
        rs0 += __shfl_xor_sync(0xffffffffu, rs0, 2);
        rs1 += __shfl_xor_sync(0xffffffffu, rs1, 1);
        rs1 += __shfl_xor_sync(0xffffffffu, rs1, 2);
        l0 = l0 * f0 + rs0;
        l1 = l1 * f1 + rs1;

#pragma unroll
        for (int nt = 0; nt < 16; nt++) {
            o[nt][0] *= f0; o[nt][1] *= f0;
            o[nt][2] *= f1; o[nt][3] *= f1;
        }

        // ---- P -> per-warp smem (A-frag source) ----
#pragma unroll
        for (int nt = 0; nt < 8; nt++) {
            *(uint2*)&Pw[lr * 68 + nt * 8 + lc * 2] =
                make_uint2(f2tf(s[nt][0]), f2tf(s[nt][1]));
            *(uint2*)&Pw[(lr + 8) * 68 + nt * 8 + lc * 2] =
                make_uint2(f2tf(s[nt][2]), f2tf(s[nt][3]));
        }
        __syncwarp();

        // ---- O += P . V ----
#pragma unroll
        for (int ks = 0; ks < 8; ks++) {
            uint32_t a[4];
            a[0] = Pw[lr * 68 + ks * 8 + lc];
            a[1] = Pw[(lr + 8) * 68 + ks * 8 + lc];
            a[2] = Pw[lr * 68 + ks * 8 + lc + 4];
            a[3] = Pw[(lr + 8) * 68 + ks * 8 + lc + 4];
#pragma unroll
            for (int nt = 0; nt < 16; nt++) {
                uint32_t bf[2];
                *(uint2*)bf = *(const uint2*)&VB[(nt * 8 + ks) * 72 + lid * 2];
                mma_tf32(o[nt], a, bf);
            }
        }

        __syncthreads();
        if (kb < qb) issueKV(kb + 1);
    }

    // ---- epilogue: g_O in [B, S, H, DHEAD] fp32 ----
    const float inv0 = 1.0f / l0;
    const float inv1 = 1.0f / l1;
    float* O0 = g_O + (((size_t)b * SEQ + row0) * NHEADS + h) * DHEAD;
    float* O1 = g_O + (((size_t)b * SEQ + row1) * NHEADS + h) * DHEAD;
#pragma unroll
    for (int nt = 0; nt < 16; nt++) {
        const int col = nt * 8 + lc * 2;
        *(float2*)(O0 + col) = make_float2(o[nt][0] * inv0, o[nt][1] * inv0);
        *(float2*)(O1 + col) = make_float2(o[nt][2] * inv1, o[nt][3] * inv1);
    }
}

// ---------------------------------------------------------------------------
// Launch
// ---------------------------------------------------------------------------
extern "C" void kernel_launch(void* const* d_in, const int* in_sizes, int n_in,
                              void* d_out, int out_size)
{
    const float* x    = (const float*)d_in[0];
    const float* Wqkv = (const float*)d_in[1];
    const float* Wout = (const float*)d_in[2];
    float* out = (float*)d_out;

    cudaFuncSetAttribute(gemm_f<1>, cudaFuncAttributeMaxDynamicSharedMemorySize, GF_SMEM);
    cudaFuncSetAttribute(gemm_f<0>, cudaFuncAttributeMaxDynamicSharedMemorySize, GF_SMEM);
    cudaFuncSetAttribute(flash_attn_v3, cudaFuncAttributeMaxDynamicSharedMemorySize, ATT3_SMEM);

    uint32_t *xf, *of, *wqf, *wof;
    cudaGetSymbolAddress((void**)&xf,  g_xf);
    cudaGetSymbolAddress((void**)&of,  g_of);
    cudaGetSymbolAddress((void**)&wqf, g_wqf);
    cudaGetSymbolAddress((void**)&wof, g_wof);
    float* oPtr = nullptr;
    cudaGetSymbolAddress((void**)&oPtr, g_O);

    // Pre-convert GEMM operands into tf32 fragment layouts
    conv_A<<<dim3(NCH, 32), 256>>>(x,    xf);
    conv_B<<<dim3(NCH, 48), 256>>>(Wqkv, wqf);
    conv_B<<<dim3(NCH, 16), 256>>>(Wout, wof);

    // Stage 1: QKV projection; epilogue emits Q/K/V tf32 fragments
    gemm_f<1><<<dim3(24, 32), 256, GF_SMEM>>>(xf, wqf, nullptr);

    // Stage 2: flash attention (fragment-fed, 2 CTAs/SM)
    flash_attn_v3<<<dim3(SEQ / 64, BATCH * NHEADS), 128, ATT3_SMEM>>>();

    // Stage 3: convert attention output, then output projection
    conv_A<<<dim3(NCH, 32), 256>>>(oPtr, of);
    gemm_f<0><<<dim3(8, 32), 256, GF_SMEM>>>(of, wof, out);
}

// round 9
// speedup vs baseline: 2.3725x; 1.8541x over previous
#include <cuda_runtime.h>
#include <cuda_fp16.h>
#include <cstdint>

// Problem constants
#define BATCH   2
#define SEQ     2048
#define DMODEL  2048
#define NHEADS  16
#define DHEAD   128

#define KC2  64                    // K elems per GEMM chunk
#define NCH2 32                    // chunks (K = 2048)

// ---------------------------------------------------------------------------
// Scratch (alloc-free: __device__ globals)
// ---------------------------------------------------------------------------
__device__ float g_O[(size_t)BATCH * SEQ * DMODEL];

// fp16 fragment-layout GEMM operands (A tile: 128 rows x 64 k = 4096 u32;
// B tile: 128 cols x 64 k = 4096 u32)
__device__ __align__(128) uint32_t g_xf [(size_t)32 * NCH2 * 4096];  // x     [4096,2048]
__device__ __align__(128) uint32_t g_of [(size_t)32 * NCH2 * 4096];  // g_O   [4096,2048]
__device__ __align__(128) uint32_t g_wqf[(size_t)48 * NCH2 * 4096];  // W_qkv [6144,2048]
__device__ __align__(128) uint32_t g_wof[(size_t)16 * NCH2 * 4096];  // W_out [2048,2048]

// fp16 fragment-layout Q/K/V (per bh, per 64-seq tile)
// Qf: 32 blocks (kt*4 + w16) x 32 lanes x 4 regs   = 4096 u32 / tile
// Kf: 64 blocks (kt*8 + s8)  x 32 lanes x 2 regs   = 4096 u32 / tile
// Vf: 64 blocks (nt*4 + ks16) x 32 lanes x 2 regs  = 4096 u32 / tile
__device__ __align__(128) uint32_t g_Qf[(size_t)32 * 32 * 4096];
__device__ __align__(128) uint32_t g_Kf[(size_t)32 * 32 * 4096];
__device__ __align__(128) uint32_t g_Vf[(size_t)32 * 32 * 4096];

__device__ __forceinline__ uint32_t pack_h2(float lo, float hi) {
    __half2 h = __floats2half2_rn(lo, hi);
    return *reinterpret_cast<uint32_t*>(&h);
}

__device__ __forceinline__ void mma_f16(float* d, const uint32_t* a, const uint32_t* b) {
    asm volatile(
        "mma.sync.aligned.m16n8k16.row.col.f32.f16.f16.f32 "
        "{%0,%1,%2,%3}, {%4,%5,%6,%7}, {%8,%9}, {%0,%1,%2,%3};"
        : "+f"(d[0]), "+f"(d[1]), "+f"(d[2]), "+f"(d[3])
        : "r"(a[0]), "r"(a[1]), "r"(a[2]), "r"(a[3]), "r"(b[0]), "r"(b[1]));
}

__device__ __forceinline__ void cpa16(uint32_t dst, const void* src) {
    asm volatile("cp.async.cg.shared.global [%0], [%1], 16;"
                 :: "r"(dst), "l"(src) : "memory");
}
#define CPA_COMMIT() asm volatile("cp.async.commit_group;" ::: "memory")
#define CPA_WAIT(n)  asm volatile("cp.async.wait_group %0;" :: "n"(n) : "memory")

__device__ __forceinline__ uint32_t smem_u32(const void* p) {
    uint32_t a;
    asm("{ .reg .u64 t; cvta.to.shared.u64 t, %1; cvt.u32.u64 %0, t; }"
        : "=r"(a) : "l"(p));
    return a;
}

// Fragment u32/u16 index helpers (element (s,d) of head-batch bh)
__device__ __forceinline__ size_t qf_u32(int bh, int s, int d) {
    return (size_t)((bh * 32 + (s >> 6)) * 32 + (d >> 4) * 4 + ((s >> 4) & 3)) * 128
         + (((s & 7) * 4 + ((d & 7) >> 1)) << 2) + (((d >> 3) & 1) << 1) + ((s >> 3) & 1);
}
__device__ __forceinline__ size_t kf_u32(int bh, int s, int d) {
    return (size_t)((bh * 32 + (s >> 6)) * 64 + (d >> 4) * 8 + ((s >> 3) & 7)) * 64
         + (((s & 7) * 4 + ((d & 7) >> 1)) << 1) + ((d >> 3) & 1);
}
__device__ __forceinline__ size_t vf_u16(int bh, int s, int d) {
    return ((size_t)((bh * 32 + (s >> 6)) * 64 + (d >> 3) * 4 + ((s >> 4) & 3)) * 64
         + (((d & 7) * 4 + ((s & 7) >> 1)) << 1) + ((s >> 3) & 1)) * 2 + (s & 1);
}

// ---------------------------------------------------------------------------
// Conversion kernels: fp32 row-major -> fp16 fragment layout (64-k chunks)
// ---------------------------------------------------------------------------
__global__ void __launch_bounds__(256)
conv_A(const float* __restrict__ src, uint32_t* __restrict__ dst)
{
    __shared__ float s[128][65];
    const int ch = blockIdx.x, mb = blockIdx.y, tid = threadIdx.x;
    const float* base = src + (size_t)mb * 128 * DMODEL + ch * KC2;
#pragma unroll
    for (int i = 0; i < 8; i++) {
        const int idx = tid + i * 256;
        const int row = idx >> 4, c4 = idx & 15;
        float4 v = *(const float4*)(base + (size_t)row * DMODEL + c4 * 4);
        s[row][c4 * 4 + 0] = v.x; s[row][c4 * 4 + 1] = v.y;
        s[row][c4 * 4 + 2] = v.z; s[row][c4 * 4 + 3] = v.w;
    }
    __syncthreads();
    uint32_t* out = dst + ((size_t)mb * NCH2 + ch) * 4096;
#pragma unroll
    for (int i = 0; i < 16; i++) {
        const int u = tid + i * 256;
        const int blk = u >> 7, rem = u & 127;
        const int lane = rem >> 2, reg = rem & 3;
        const int gm = blk >> 2, ks = blk & 3;
        const int r = (reg & 1) * 8 + (lane >> 2);
        const int c = (reg >> 1) * 8 + (lane & 3) * 2;
        const int k = ks * 16 + c;
        out[u] = pack_h2(s[gm * 16 + r][k], s[gm * 16 + r][k + 1]);
    }
}

__global__ void __launch_bounds__(256)
conv_B(const float* __restrict__ src, uint32_t* __restrict__ dst)
{
    __shared__ float s[128][65];
    const int ch = blockIdx.x, nb = blockIdx.y, tid = threadIdx.x;
    const float* base = src + (size_t)nb * 128 * DMODEL + ch * KC2;
#pragma unroll
    for (int i = 0; i < 8; i++) {
        const int idx = tid + i * 256;
        const int row = idx >> 4, c4 = idx & 15;
        float4 v = *(const float4*)(base + (size_t)row * DMODEL + c4 * 4);
        s[row][c4 * 4 + 0] = v.x; s[row][c4 * 4 + 1] = v.y;
        s[row][c4 * 4 + 2] = v.z; s[row][c4 * 4 + 3] = v.w;
    }
    __syncthreads();
    uint32_t* out = dst + ((size_t)nb * NCH2 + ch) * 4096;
#pragma unroll
    for (int i = 0; i < 16; i++) {
        const int u = tid + i * 256;
        const int blk = u >> 6, rem = u & 63;
        const int lane = rem >> 1, reg = rem & 1;
        const int gn = blk >> 2, ks = blk & 3;
        const int n = lane >> 2, tig = lane & 3;
        const int k = ks * 16 + reg * 8 + tig * 2;
        out[u] = pack_h2(s[gn * 8 + n][k], s[gn * 8 + n][k + 1]);
    }
}

// ---------------------------------------------------------------------------
// Fragment-fed fp16 GEMM: C[m,n] = sum_k A[m,k]*B[n,k], K = 2048.
// CTA 128(m) x 256(n), 8 warps (2m x 4n), warp tile 64x64, m16n8k16.
// K-chunk 64, 4-stage cp.async ring, prefetch distance 2, 1 barrier/chunk.
// MODE 0: C row-major [M, 2048]. MODE 1: emit Q/K/V fp16 fragments.
// ---------------------------------------------------------------------------
#define STAGE_U32 12288
#define GF_SMEM   (4 * STAGE_U32 * 4)    // 196608 bytes

template <int MODE>
__global__ void __launch_bounds__(256)
gemm_h(const uint32_t* __restrict__ Af, const uint32_t* __restrict__ Bf,
       float* __restrict__ C)
{
    extern __shared__ uint32_t us[];
    const int tid = threadIdx.x;
    const int wid = tid >> 5;
    const int lid = tid & 31;
    const int wm  = wid & 1;
    const int wn  = wid >> 1;
    const int mb  = blockIdx.y;
    const int nbx = blockIdx.x;
    const uint32_t sb = smem_u32(us);

    float acc[4][8][4];
#pragma unroll
    for (int i = 0; i < 4; i++)
#pragma unroll
        for (int j = 0; j < 8; j++)
#pragma unroll
            for (int v = 0; v < 4; v++) acc[i][j][v] = 0.0f;

    auto issue = [&](int c, int st) {
        const uint32_t sA = sb + st * (STAGE_U32 * 4);
        const uint32_t sB = sA + 16384;
        const uint32_t* gA  = Af + ((size_t)mb * NCH2 + c) * 4096;
        const uint32_t* gB0 = Bf + ((size_t)(2 * nbx)     * NCH2 + c) * 4096;
        const uint32_t* gB1 = Bf + ((size_t)(2 * nbx + 1) * NCH2 + c) * 4096;
#pragma unroll
        for (int i = 0; i < 4; i++) {
            const int o = tid + i * 256;
            cpa16(sA + o * 16, gA + (size_t)o * 4);
        }
#pragma unroll
        for (int i = 0; i < 4; i++) {
            const int o = tid + i * 256;
            cpa16(sB + o * 16, gB0 + (size_t)o * 4);
        }
#pragma unroll
        for (int i = 0; i < 4; i++) {
            const int o = tid + i * 256;
            cpa16(sB + 16384 + o * 16, gB1 + (size_t)o * 4);
        }
        CPA_COMMIT();
    };

    issue(0, 0);
    issue(1, 1);

    for (int c = 0; c < NCH2; ++c) {
        const int st = c & 3;
        if (c + 2 < NCH2)      { issue(c + 2, (c + 2) & 3); CPA_WAIT(2); }
        else if (c + 1 < NCH2) { CPA_WAIT(1); }
        else                   { CPA_WAIT(0); }
        __syncthreads();

        const uint32_t* uA = us + st * STAGE_U32;
        const uint32_t* uB = uA + 4096;
#pragma unroll
        for (int ks = 0; ks < 4; ks++) {
            uint4 a[4];
            uint32_t b[8][2];
#pragma unroll
            for (int mt = 0; mt < 4; mt++)
                a[mt] = *(const uint4*)&uA[(((wm * 4 + mt) * 4 + ks) * 32 + lid) * 4];
#pragma unroll
            for (int nt = 0; nt < 8; nt++) {
                const int gn = wn * 8 + nt;
                *(uint2*)b[nt] = *(const uint2*)
                    &uB[(gn >> 4) * 4096 + (((gn & 15) * 4 + ks) * 32 + lid) * 2];
            }
#pragma unroll
            for (int mt = 0; mt < 4; mt++)
#pragma unroll
                for (int nt = 0; nt < 8; nt++)
                    mma_f16(acc[mt][nt], (const uint32_t*)&a[mt], b[nt]);
        }
    }

    // ---- epilogue ----
    const int lr  = lid >> 2;
    const int lc2 = (lid & 3) * 2;
    const int m0  = mb * 128;
    const int n0  = nbx * 256;
    const int t   = n0 >> 11;                  // uniform per CTA (0=Q,1=K,2=V)
    __half* vh = (__half*)g_Vf;
#pragma unroll
    for (int mt = 0; mt < 4; mt++) {
        const int m = m0 + wm * 64 + mt * 16 + lr;
#pragma unroll
        for (int nt = 0; nt < 8; nt++) {
            const int cg = n0 + wn * 64 + nt * 8 + lc2;
            if (MODE == 0) {
                float* dst = C + (size_t)m * DMODEL + cg;
                *(float2*)dst                         = make_float2(acc[mt][nt][0], acc[mt][nt][1]);
                *(float2*)(dst + (size_t)8 * DMODEL)  = make_float2(acc[mt][nt][2], acc[mt][nt][3]);
            } else {
                const int h  = (cg >> 7) & (NHEADS - 1);
                const int d  = cg & (DHEAD - 1);
                const int b  = m >> 11;
                const int s  = m & (SEQ - 1);
                const int bh = b * NHEADS + h;
                if (t == 0) {
                    g_Qf[qf_u32(bh, s,     d)] = pack_h2(acc[mt][nt][0], acc[mt][nt][1]);
                    g_Qf[qf_u32(bh, s + 8, d)] = pack_h2(acc[mt][nt][2], acc[mt][nt][3]);
                } else if (t == 1) {
                    g_Kf[kf_u32(bh, s,     d)] = pack_h2(acc[mt][nt][0], acc[mt][nt][1]);
                    g_Kf[kf_u32(bh, s + 8, d)] = pack_h2(acc[mt][nt][2], acc[mt][nt][3]);
                } else {
                    vh[vf_u16(bh, s,     d    )] = __float2half_rn(acc[mt][nt][0]);
                    vh[vf_u16(bh, s,     d + 1)] = __float2half_rn(acc[mt][nt][1]);
                    vh[vf_u16(bh, s + 8, d    )] = __float2half_rn(acc[mt][nt][2]);
                    vh[vf_u16(bh, s + 8, d + 1)] = __float2half_rn(acc[mt][nt][3]);
                }
            }
        }
    }
}

// ---------------------------------------------------------------------------
// Flash attention v4 (fp16 fragments): 128-thread CTAs, 64-row Q tiles,
// Q in registers, 2-stage cp.async K/V ring (overlap load with compute).
// ---------------------------------------------------------------------------
#define KV_U32   4096                       // one K (or V) tile: 16 KB
#define ATT_SMEM ((2 * 2 * KV_U32 + 4 * 576) * 4)   // 74752 bytes

__global__ void __launch_bounds__(128)
flash_attn_v4()
{
    extern __shared__ uint32_t sm32[];
    const int tid = threadIdx.x;
    const int wid = tid >> 5;
    const int lid = tid & 31;
    const int qb  = gridDim.x - 1 - blockIdx.x;   // big tiles first
    const int bh  = blockIdx.y;
    const int q0  = qb * 64;
    const int b   = bh >> 4;
    const int h   = bh & (NHEADS - 1);
    uint32_t* Pw = sm32 + 4 * KV_U32 + wid * 576; // 16 rows x 36 u32 (pad)
    const uint32_t sb = smem_u32(sm32);

    // ---- Q fragments into registers ----
    uint32_t q[8][4];
    {
        const uint4* qg = (const uint4*)(g_Qf + (size_t)(bh * 32 + qb) * 4096);
#pragma unroll
        for (int kt = 0; kt < 8; kt++) {
            uint4 v = __ldg(&qg[(kt * 4 + wid) * 32 + lid]);
            q[kt][0] = v.x; q[kt][1] = v.y; q[kt][2] = v.z; q[kt][3] = v.w;
        }
    }

    auto issueKV = [&](int kb, int st) {
        const uint4* gk = (const uint4*)(g_Kf + (size_t)(bh * 32 + kb) * KV_U32);
        const uint4* gv = (const uint4*)(g_Vf + (size_t)(bh * 32 + kb) * KV_U32);
        const uint32_t base = sb + st * (2 * KV_U32 * 4);
#pragma unroll
        for (int i = 0; i < 8; i++)
            cpa16(base + (tid + i * 128) * 16, gk + tid + i * 128);
#pragma unroll
        for (int i = 0; i < 8; i++)
            cpa16(base + KV_U32 * 4 + (tid + i * 128) * 16, gv + tid + i * 128);
        CPA_COMMIT();
    };

    float o[16][4];
#pragma unroll
    for (int nt = 0; nt < 16; nt++)
#pragma unroll
        for (int v = 0; v < 4; v++) o[nt][v] = 0.0f;

    float mx0 = -1e30f, mx1 = -1e30f, l0 = 0.0f, l1 = 0.0f;
    const float scale = 0.08838834764831845f;   // 1/sqrt(128)
    const int lr = lid >> 2;
    const int lc = lid & 3;
    const int row0 = q0 + wid * 16 + lr;
    const int row1 = row0 + 8;

    issueKV(0, 0);

    for (int kb = 0; kb <= qb; kb++) {
        if (kb + 1 <= qb) { issueKV(kb + 1, (kb + 1) & 1); CPA_WAIT(1); }
        else              { CPA_WAIT(0); }
        __syncthreads();

        const uint32_t* KB = sm32 + (kb & 1) * 2 * KV_U32;
        const uint32_t* VB = KB + KV_U32;

        // ---- S = Q . K^T : 16 rows x 64 cols per warp ----
        float s[8][4];
#pragma unroll
        for (int nt = 0; nt < 8; nt++)
#pragma unroll
            for (int v = 0; v < 4; v++) s[nt][v] = 0.0f;

#pragma unroll
        for (int kt = 0; kt < 8; kt++)
#pragma unroll
            for (int nt = 0; nt < 8; nt++) {
                uint32_t bf[2];
                *(uint2*)bf = *(const uint2*)&KB[(kt * 8 + nt) * 64 + lid * 2];
                mma_f16(s[nt], q[kt], bf);
            }

        // ---- scale + causal mask (diagonal block) + online softmax ----
        const bool domask = (kb == qb);
        const int k0 = kb * 64;
        float ml0 = -1e30f, ml1 = -1e30f;
#pragma unroll
        for (int nt = 0; nt < 8; nt++) {
            const int c0 = k0 + nt * 8 + lc * 2;
            s[nt][0] *= scale; s[nt][1] *= scale;
            s[nt][2] *= scale; s[nt][3] *= scale;
            if (domask) {
                if (c0     > row0) s[nt][0] = -1e30f;
                if (c0 + 1 > row0) s[nt][1] = -1e30f;
                if (c0     > row1) s[nt][2] = -1e30f;
                if (c0 + 1 > row1) s[nt][3] = -1e30f;
            }
            ml0 = fmaxf(ml0, fmaxf(s[nt][0], s[nt][1]));
            ml1 = fmaxf(ml1, fmaxf(s[nt][2], s[nt][3]));
        }
        ml0 = fmaxf(ml0, __shfl_xor_sync(0xffffffffu, ml0, 1));
        ml0 = fmaxf(ml0, __shfl_xor_sync(0xffffffffu, ml0, 2));
        ml1 = fmaxf(ml1, __shfl_xor_sync(0xffffffffu, ml1, 1));
        ml1 = fmaxf(ml1, __shfl_xor_sync(0xffffffffu, ml1, 2));

        const float mn0 = fmaxf(mx0, ml0);
        const float mn1 = fmaxf(mx1, ml1);
        const float f0 = __expf(mx0 - mn0);
        const float f1 = __expf(mx1 - mn1);
        mx0 = mn0; mx1 = mn1;

        float rs0 = 0.0f, rs1 = 0.0f;
#pragma unroll
        for (int nt = 0; nt < 8; nt++) {
            s[nt][0] = __expf(s[nt][0] - mn0);
            s[nt][1] = __expf(s[nt][1] - mn0);
            s[nt][2] = __expf(s[nt][2] - mn1);
            s[nt][3] = __expf(s[nt][3] - mn1);
            rs0 += s[nt][0] + s[nt][1];
            rs1 += s[nt][2] + s[nt][3];
        }
        rs0 += __shfl_xor_sync(0xffffffffu, rs0, 1);
        rs0 += __shfl_xor_sync(0xffffffffu, rs0, 2);
        rs1 += __shfl_xor_sync(0xffffffffu, rs1, 1);
        rs1 += __shfl_xor_sync(0xffffffffu, rs1, 2);
        l0 = l0 * f0 + rs0;
        l1 = l1 * f1 + rs1;

#pragma unroll
        for (int nt = 0; nt < 16; nt++) {
            o[nt][0] *= f0; o[nt][1] *= f0;
            o[nt][2] *= f1; o[nt][3] *= f1;
        }

        // ---- P (fp16) -> per-warp smem as A-frag halves ----
#pragma unroll
        for (int nt = 0; nt < 8; nt++) {
            Pw[lr * 36 + nt * 4 + lc]       = pack_h2(s[nt][0], s[nt][1]);
            Pw[(lr + 8) * 36 + nt * 4 + lc] = pack_h2(s[nt][2], s[nt][3]);
        }
        __syncwarp();

        // ---- O += P . V ----
#pragma unroll
        for (int ks2 = 0; ks2 < 4; ks2++) {
            uint32_t a[4];
            a[0] = Pw[lr * 36 + ks2 * 8 + lc];
            a[1] = Pw[(lr + 8) * 36 + ks2 * 8 + lc];
            a[2] = Pw[lr * 36 + ks2 * 8 + lc + 4];
            a[3] = Pw[(lr + 8) * 36 + ks2 * 8 + lc + 4];
#pragma unroll
            for (int nt = 0; nt < 16; nt++) {
                uint32_t bf[2];
                *(uint2*)bf = *(const uint2*)&VB[(nt * 4 + ks2) * 64 + lid * 2];
                mma_f16(o[nt], a, bf);
            }
        }
        __syncthreads();   // protect KV stage before re-issue
    }

    // ---- epilogue: g_O in [B, S, H, DHEAD] fp32 ----
    const float inv0 = 1.0f / l0;
    const float inv1 = 1.0f / l1;
    float* O0 = g_O + (((size_t)b * SEQ + row0) * NHEADS + h) * DHEAD;
    float* O1 = g_O + (((size_t)b * SEQ + row1) * NHEADS + h) * DHEAD;
#pragma unroll
    for (int nt = 0; nt < 16; nt++) {
        const int col = nt * 8 + lc * 2;
        *(float2*)(O0 + col) = make_float2(o[nt][0] * inv0, o[nt][1] * inv0);
        *(float2*)(O1 + col) = make_float2(o[nt][2] * inv1, o[nt][3] * inv1);
    }
}

// ---------------------------------------------------------------------------
// Launch
// ---------------------------------------------------------------------------
extern "C" void kernel_launch(void* const* d_in, const int* in_sizes, int n_in,
                              void* d_out, int out_size)
{
    const float* x    = (const float*)d_in[0];
    const float* Wqkv = (const float*)d_in[1];
    const float* Wout = (const float*)d_in[2];
    float* out = (float*)d_out;

    cudaFuncSetAttribute(gemm_h<1>, cudaFuncAttributeMaxDynamicSharedMemorySize, GF_SMEM);
    cudaFuncSetAttribute(gemm_h<0>, cudaFuncAttributeMaxDynamicSharedMemorySize, GF_SMEM);
    cudaFuncSetAttribute(flash_attn_v4, cudaFuncAttributeMaxDynamicSharedMemorySize, ATT_SMEM);

    uint32_t *xf, *of, *wqf, *wof;
    cudaGetSymbolAddress((void**)&xf,  g_xf);
    cudaGetSymbolAddress((void**)&of,  g_of);
    cudaGetSymbolAddress((void**)&wqf, g_wqf);
    cudaGetSymbolAddress((void**)&wof, g_wof);
    float* oPtr = nullptr;
    cudaGetSymbolAddress((void**)&oPtr, g_O);

    // Pre-convert GEMM operands into fp16 fragment layouts
    conv_A<<<dim3(NCH2, 32), 256>>>(x,    xf);
    conv_B<<<dim3(NCH2, 48), 256>>>(Wqkv, wqf);
    conv_B<<<dim3(NCH2, 16), 256>>>(Wout, wof);

    // Stage 1: QKV projection; epilogue emits Q/K/V fp16 fragments
    gemm_h<1><<<dim3(24, 32), 256, GF_SMEM>>>(xf, wqf, nullptr);

    // Stage 2: flash attention (fp16 fragments, double-buffered KV)
    flash_attn_v4<<<dim3(32, BATCH * NHEADS), 128, ATT_SMEM>>>();

    // Stage 3: convert attention output, then output projection
    conv_A<<<dim3(NCH2, 32), 256>>>(oPtr, of);
    gemm_h<0><<<dim3(8, 32), 256, GF_SMEM>>>(of, wof, out);
}

// round 10
// speedup vs baseline: 2.5007x; 1.0540x over previous
#include <cuda_runtime.h>
#include <cuda_fp16.h>
#include <cstdint>

// Problem constants
#define BATCH   2
#define SEQ     2048
#define DMODEL  2048
#define NHEADS  16
#define DHEAD   128

#define KC2  64                    // K elems per GEMM chunk
#define NCH2 32                    // chunks (K = 2048)

// ---------------------------------------------------------------------------
// Scratch (alloc-free: __device__ globals)
// ---------------------------------------------------------------------------
// fp16 fragment-layout GEMM operands
__device__ __align__(128) uint32_t g_xf [(size_t)32 * NCH2 * 4096];  // x     [4096,2048]
__device__ __align__(128) uint32_t g_of [(size_t)32 * NCH2 * 4096];  // attn out [4096,2048]
__device__ __align__(128) uint32_t g_wqf[(size_t)48 * NCH2 * 4096];  // W_qkv [6144,2048]
__device__ __align__(128) uint32_t g_wof[(size_t)16 * NCH2 * 4096];  // W_out [2048,2048]

// fp16 fragment-layout Q/K/V (per bh, per 64-seq tile)
__device__ __align__(128) uint32_t g_Qf[(size_t)32 * 32 * 4096];
__device__ __align__(128) uint32_t g_Kf[(size_t)32 * 32 * 4096];
__device__ __align__(128) uint32_t g_Vf[(size_t)32 * 32 * 4096];

__device__ __forceinline__ uint32_t pack_h2(float lo, float hi) {
    __half2 h = __floats2half2_rn(lo, hi);
    return *reinterpret_cast<uint32_t*>(&h);
}

__device__ __forceinline__ void mma_f16(float* d, const uint32_t* a, const uint32_t* b) {
    asm volatile(
        "mma.sync.aligned.m16n8k16.row.col.f32.f16.f16.f32 "
        "{%0,%1,%2,%3}, {%4,%5,%6,%7}, {%8,%9}, {%0,%1,%2,%3};"
        : "+f"(d[0]), "+f"(d[1]), "+f"(d[2]), "+f"(d[3])
        : "r"(a[0]), "r"(a[1]), "r"(a[2]), "r"(a[3]), "r"(b[0]), "r"(b[1]));
}

__device__ __forceinline__ void cpa16(uint32_t dst, const void* src) {
    asm volatile("cp.async.cg.shared.global [%0], [%1], 16;"
                 :: "r"(dst), "l"(src) : "memory");
}
#define CPA_COMMIT() asm volatile("cp.async.commit_group;" ::: "memory")
#define CPA_WAIT(n)  asm volatile("cp.async.wait_group %0;" :: "n"(n) : "memory")

__device__ __forceinline__ uint32_t smem_u32(const void* p) {
    uint32_t a;
    asm("{ .reg .u64 t; cvta.to.shared.u64 t, %1; cvt.u32.u64 %0, t; }"
        : "=r"(a) : "l"(p));
    return a;
}

// Fragment index helpers (element (s,d) of head-batch bh)
__device__ __forceinline__ size_t qf_u32(int bh, int s, int d) {
    return (size_t)((bh * 32 + (s >> 6)) * 32 + (d >> 4) * 4 + ((s >> 4) & 3)) * 128
         + (((s & 7) * 4 + ((d & 7) >> 1)) << 2) + (((d >> 3) & 1) << 1) + ((s >> 3) & 1);
}
__device__ __forceinline__ size_t kf_u32(int bh, int s, int d) {
    return (size_t)((bh * 32 + (s >> 6)) * 64 + (d >> 4) * 8 + ((s >> 3) & 7)) * 64
         + (((s & 7) * 4 + ((d & 7) >> 1)) << 1) + ((d >> 3) & 1);
}
__device__ __forceinline__ size_t vf_u16(int bh, int s, int d) {
    return ((size_t)((bh * 32 + (s >> 6)) * 64 + (d >> 3) * 4 + ((s >> 4) & 3)) * 64
         + (((d & 7) * 4 + ((s & 7) >> 1)) << 1) + ((s >> 3) & 1)) * 2 + (s & 1);
}

// ---------------------------------------------------------------------------
// Conversion kernels: fp32 row-major -> fp16 fragment layout (64-k chunks)
// ---------------------------------------------------------------------------
__global__ void __launch_bounds__(256)
conv_A(const float* __restrict__ src, uint32_t* __restrict__ dst)
{
    __shared__ float s[128][65];
    const int ch = blockIdx.x, mb = blockIdx.y, tid = threadIdx.x;
    const float* base = src + (size_t)mb * 128 * DMODEL + ch * KC2;
#pragma unroll
    for (int i = 0; i < 8; i++) {
        const int idx = tid + i * 256;
        const int row = idx >> 4, c4 = idx & 15;
        float4 v = *(const float4*)(base + (size_t)row * DMODEL + c4 * 4);
        s[row][c4 * 4 + 0] = v.x; s[row][c4 * 4 + 1] = v.y;
        s[row][c4 * 4 + 2] = v.z; s[row][c4 * 4 + 3] = v.w;
    }
    __syncthreads();
    uint32_t* out = dst + ((size_t)mb * NCH2 + ch) * 4096;
#pragma unroll
    for (int i = 0; i < 16; i++) {
        const int u = tid + i * 256;
        const int blk = u >> 7, rem = u & 127;
        const int lane = rem >> 2, reg = rem & 3;
        const int gm = blk >> 2, ks = blk & 3;
        const int r = (reg & 1) * 8 + (lane >> 2);
        const int c = (reg >> 1) * 8 + (lane & 3) * 2;
        const int k = ks * 16 + c;
        out[u] = pack_h2(s[gm * 16 + r][k], s[gm * 16 + r][k + 1]);
    }
}

__global__ void __launch_bounds__(256)
conv_B(const float* __restrict__ src, uint32_t* __restrict__ dst)
{
    __shared__ float s[128][65];
    const int ch = blockIdx.x, nb = blockIdx.y, tid = threadIdx.x;
    const float* base = src + (size_t)nb * 128 * DMODEL + ch * KC2;
#pragma unroll
    for (int i = 0; i < 8; i++) {
        const int idx = tid + i * 256;
        const int row = idx >> 4, c4 = idx & 15;
        float4 v = *(const float4*)(base + (size_t)row * DMODEL + c4 * 4);
        s[row][c4 * 4 + 0] = v.x; s[row][c4 * 4 + 1] = v.y;
        s[row][c4 * 4 + 2] = v.z; s[row][c4 * 4 + 3] = v.w;
    }
    __syncthreads();
    uint32_t* out = dst + ((size_t)nb * NCH2 + ch) * 4096;
#pragma unroll
    for (int i = 0; i < 16; i++) {
        const int u = tid + i * 256;
        const int blk = u >> 6, rem = u & 63;
        const int lane = rem >> 1, reg = rem & 1;
        const int gn = blk >> 2, ks = blk & 3;
        const int n = lane >> 2, tig = lane & 3;
        const int k = ks * 16 + reg * 8 + tig * 2;
        out[u] = pack_h2(s[gn * 8 + n][k], s[gn * 8 + n][k + 1]);
    }
}

// ---------------------------------------------------------------------------
// Fragment-fed fp16 GEMM: C[m,n] = sum_k A[m,k]*B[n,k], K = 2048.
// CTA 128(m) x (NNT*32)(n), 8 warps (2m x 4n), warp tile 64 x NNT*8.
// B fetched at 64-col (8KB) granularity so any NNT works.
// MODE 0: C row-major [M, 2048]. MODE 1: emit Q/K/V fp16 fragments
//         (tensor/head boundaries resolved per element).
// ---------------------------------------------------------------------------
#define GF_SMEM_MAX (4 * (4096 + 4 * 2048) * 4)    // 196608 bytes (NNT=8)

template <int MODE, int NNT>
__global__ void __launch_bounds__(256)
gemm_h(const uint32_t* __restrict__ Af, const uint32_t* __restrict__ Bf,
       float* __restrict__ C)
{
    constexpr int NBT64 = NNT / 2;                 // 64-col chunks per CTA tile
    constexpr int STG   = 4096 + NBT64 * 2048;     // stage size in u32

    extern __shared__ uint32_t us[];
    const int tid = threadIdx.x;
    const int wid = tid >> 5;
    const int lid = tid & 31;
    const int wm  = wid & 1;
    const int wn  = wid >> 1;
    const int mb  = blockIdx.y;
    const int nbx = blockIdx.x;
    const int n0  = nbx * (NNT * 32);
    const uint32_t sb = smem_u32(us);

    float acc[4][NNT][4];
#pragma unroll
    for (int i = 0; i < 4; i++)
#pragma unroll
        for (int j = 0; j < NNT; j++)
#pragma unroll
            for (int v = 0; v < 4; v++) acc[i][j][v] = 0.0f;

    auto issue = [&](int c, int st) {
        const uint32_t sA = sb + st * (STG * 4);
        const uint32_t sB = sA + 16384;
        const uint32_t* gA = Af + ((size_t)mb * NCH2 + c) * 4096;
#pragma unroll
        for (int i = 0; i < 4; i++) {
            const int o = tid + i * 256;
            cpa16(sA + o * 16, gA + (size_t)o * 4);
        }
#pragma unroll
        for (int j = 0; j < NBT64; j++) {
            const int c64 = (n0 >> 6) + j;
            const uint32_t* gB = Bf + ((size_t)(c64 >> 1) * NCH2 + c) * 4096
                                    + (c64 & 1) * 2048;
#pragma unroll
            for (int i = 0; i < 2; i++) {
                const int o = tid + i * 256;
                cpa16(sB + j * 8192 + o * 16, gB + (size_t)o * 4);
            }
        }
        CPA_COMMIT();
    };

    issue(0, 0);
    issue(1, 1);

    for (int c = 0; c < NCH2; ++c) {
        const int st = c & 3;
        if (c + 2 < NCH2)      { issue(c + 2, (c + 2) & 3); CPA_WAIT(2); }
        else if (c + 1 < NCH2) { CPA_WAIT(1); }
        else                   { CPA_WAIT(0); }
        __syncthreads();

        const uint32_t* uA = us + st * STG;
        const uint32_t* uB = uA + 4096;
#pragma unroll
        for (int ks = 0; ks < 4; ks++) {
            uint4 a[4];
            uint32_t b[NNT][2];
#pragma unroll
            for (int mt = 0; mt < 4; mt++)
                a[mt] = *(const uint4*)&uA[(((wm * 4 + mt) * 4 + ks) * 32 + lid) * 4];
#pragma unroll
            for (int nt = 0; nt < NNT; nt++) {
                const int col = wn * (NNT * 8) + nt * 8;
                *(uint2*)b[nt] = *(const uint2*)
                    &uB[(col >> 6) * 2048 + ((((col >> 3) & 7) * 4 + ks) * 64) + lid * 2];
            }
#pragma unroll
            for (int mt = 0; mt < 4; mt++)
#pragma unroll
                for (int nt = 0; nt < NNT; nt++)
                    mma_f16(acc[mt][nt], (const uint32_t*)&a[mt], b[nt]);
        }
    }

    // ---- epilogue ----
    const int lr  = lid >> 2;
    const int lc2 = (lid & 3) * 2;
    const int m0  = mb * 128;
    __half* vh = (__half*)g_Vf;
#pragma unroll
    for (int mt = 0; mt < 4; mt++) {
        const int m = m0 + wm * 64 + mt * 16 + lr;
#pragma unroll
        for (int nt = 0; nt < NNT; nt++) {
            const int cg = n0 + wn * (NNT * 8) + nt * 8 + lc2;
            if (MODE == 0) {
                float* dst = C + (size_t)m * DMODEL + cg;
                *(float2*)dst                         = make_float2(acc[mt][nt][0], acc[mt][nt][1]);
                *(float2*)(dst + (size_t)8 * DMODEL)  = make_float2(acc[mt][nt][2], acc[mt][nt][3]);
            } else {
                const int t  = cg >> 11;               // 0=Q,1=K,2=V
                const int h  = (cg >> 7) & (NHEADS - 1);
                const int d  = cg & (DHEAD - 1);
                const int b  = m >> 11;
                const int s  = m & (SEQ - 1);
                const int bh = b * NHEADS + h;
                if (t == 0) {
                    g_Qf[qf_u32(bh, s,     d)] = pack_h2(acc[mt][nt][0], acc[mt][nt][1]);
                    g_Qf[qf_u32(bh, s + 8, d)] = pack_h2(acc[mt][nt][2], acc[mt][nt][3]);
                } else if (t == 1) {
                    g_Kf[kf_u32(bh, s,     d)] = pack_h2(acc[mt][nt][0], acc[mt][nt][1]);
                    g_Kf[kf_u32(bh, s + 8, d)] = pack_h2(acc[mt][nt][2], acc[mt][nt][3]);
                } else {
                    vh[vf_u16(bh, s,     d    )] = __float2half_rn(acc[mt][nt][0]);
                    vh[vf_u16(bh, s,     d + 1)] = __float2half_rn(acc[mt][nt][1]);
                    vh[vf_u16(bh, s + 8, d    )] = __float2half_rn(acc[mt][nt][2]);
                    vh[vf_u16(bh, s + 8, d + 1)] = __float2half_rn(acc[mt][nt][3]);
                }
            }
        }
    }
}

// ---------------------------------------------------------------------------
// Flash attention v5 (fp16 fragments): 128-thread CTAs, 64-row Q tiles,
// Q in registers, 2-stage cp.async K/V ring. Epilogue writes the out-proj
// A-operand fragments (g_of) DIRECTLY — no fp32 intermediate, no conv pass.
// ---------------------------------------------------------------------------
#define KV_U32   4096                       // one K (or V) tile: 16 KB
#define ATT_SMEM ((2 * 2 * KV_U32 + 4 * 576) * 4)   // 74752 bytes

__global__ void __launch_bounds__(128)
flash_attn_v5()
{
    extern __shared__ uint32_t sm32[];
    const int tid = threadIdx.x;
    const int wid = tid >> 5;
    const int lid = tid & 31;
    const int qb  = gridDim.x - 1 - blockIdx.x;   // big tiles first
    const int bh  = blockIdx.y;
    const int b   = bh >> 4;
    const int h   = bh & (NHEADS - 1);
    uint32_t* Pw = sm32 + 4 * KV_U32 + wid * 576;
    const uint32_t sb = smem_u32(sm32);

    // ---- Q fragments into registers ----
    uint32_t q[8][4];
    {
        const uint4* qg = (const uint4*)(g_Qf + (size_t)(bh * 32 + qb) * 4096);
#pragma unroll
        for (int kt = 0; kt < 8; kt++) {
            uint4 v = __ldg(&qg[(kt * 4 + wid) * 32 + lid]);
            q[kt][0] = v.x; q[kt][1] = v.y; q[kt][2] = v.z; q[kt][3] = v.w;
        }
    }

    auto issueKV = [&](int kb, int st) {
        const uint4* gk = (const uint4*)(g_Kf + (size_t)(bh * 32 + kb) * KV_U32);
        const uint4* gv = (const uint4*)(g_Vf + (size_t)(bh * 32 + kb) * KV_U32);
        const uint32_t base = sb + st * (2 * KV_U32 * 4);
#pragma unroll
        for (int i = 0; i < 8; i++)
            cpa16(base + (tid + i * 128) * 16, gk + tid + i * 128);
#pragma unroll
        for (int i = 0; i < 8; i++)
            cpa16(base + KV_U32 * 4 + (tid + i * 128) * 16, gv + tid + i * 128);
        CPA_COMMIT();
    };

    float o[16][4];
#pragma unroll
    for (int nt = 0; nt < 16; nt++)
#pragma unroll
        for (int v = 0; v < 4; v++) o[nt][v] = 0.0f;

    float mx0 = -1e30f, mx1 = -1e30f, l0 = 0.0f, l1 = 0.0f;
    const float scale = 0.08838834764831845f;   // 1/sqrt(128)
    const int lr = lid >> 2;
    const int lc = lid & 3;
    const int q0 = qb * 64;
    const int row0 = q0 + wid * 16 + lr;
    const int row1 = row0 + 8;

    issueKV(0, 0);

    for (int kb = 0; kb <= qb; kb++) {
        if (kb + 1 <= qb) { issueKV(kb + 1, (kb + 1) & 1); CPA_WAIT(1); }
        else              { CPA_WAIT(0); }
        __syncthreads();

        const uint32_t* KB = sm32 + (kb & 1) * 2 * KV_U32;
        const uint32_t* VB = KB + KV_U32;

        float s[8][4];
#pragma unroll
        for (int nt = 0; nt < 8; nt++)
#pragma unroll
            for (int v = 0; v < 4; v++) s[nt][v] = 0.0f;

#pragma unroll
        for (int kt = 0; kt < 8; kt++)
#pragma unroll
            for (int nt = 0; nt < 8; nt++) {
                uint32_t bf[2];
                *(uint2*)bf = *(const uint2*)&KB[(kt * 8 + nt) * 64 + lid * 2];
                mma_f16(s[nt], q[kt], bf);
            }

        const bool domask = (kb == qb);
        const int k0 = kb * 64;
        float ml0 = -1e30f, ml1 = -1e30f;
#pragma unroll
        for (int nt = 0; nt < 8; nt++) {
            const int c0 = k0 + nt * 8 + lc * 2;
            s[nt][0] *= scale; s[nt][1] *= scale;
            s[nt][2] *= scale; s[nt][3] *= scale;
            if (domask) {
                if (c0     > row0) s[nt][0] = -1e30f;
                if (c0 + 1 > row0) s[nt][1] = -1e30f;
                if (c0     > row1) s[nt][2] = -1e30f;
                if (c0 + 1 > row1) s[nt][3] = -1e30f;
            }
            ml0 = fmaxf(ml0, fmaxf(s[nt][0], s[nt][1]));
            ml1 = fmaxf(ml1, fmaxf(s[nt][2], s[nt][3]));
        }
        ml0 = fmaxf(ml0, __shfl_xor_sync(0xffffffffu, ml0, 1));
        ml0 = fmaxf(ml0, __shfl_xor_sync(0xffffffffu, ml0, 2));
        ml1 = fmaxf(ml1, __shfl_xor_sync(0xffffffffu, ml1, 1));
        ml1 = fmaxf(ml1, __shfl_xor_sync(0xffffffffu, ml1, 2));

        const float mn0 = fmaxf(mx0, ml0);
        const float mn1 = fmaxf(mx1, ml1);
        const float f0 = __expf(mx0 - mn0);
        const float f1 = __expf(mx1 - mn1);
        mx0 = mn0; mx1 = mn1;

        float rs0 = 0.0f, rs1 = 0.0f;
#pragma unroll
        for (int nt = 0; nt < 8; nt++) {
            s[nt][0] = __expf(s[nt][0] - mn0);
            s[nt][1] = __expf(s[nt][1] - mn0);
            s[nt][2] = __expf(s[nt][2] - mn1);
            s[nt][3] = __expf(s[nt][3] - mn1);
            rs0 += s[nt][0] + s[nt][1];
            rs1 += s[nt][2] + s[nt][3];
        }
        rs0 += __shfl_xor_sync(0xffffffffu, rs0, 1);
        rs0 += __shfl_xor_sync(0xffffffffu, rs0, 2);
        rs1 += __shfl_xor_sync(0xffffffffu, rs1, 1);
        rs1 += __shfl_xor_sync(0xffffffffu, rs1, 2);
        l0 = l0 * f0 + rs0;
        l1 = l1 * f1 + rs1;

#pragma unroll
        for (int nt = 0; nt < 16; nt++) {
            o[nt][0] *= f0; o[nt][1] *= f0;
            o[nt][2] *= f1; o[nt][3] *= f1;
        }

#pragma unroll
        for (int nt = 0; nt < 8; nt++) {
            Pw[lr * 36 + nt * 4 + lc]       = pack_h2(s[nt][0], s[nt][1]);
            Pw[(lr + 8) * 36 + nt * 4 + lc] = pack_h2(s[nt][2], s[nt][3]);
        }
        __syncwarp();

#pragma unroll
        for (int ks2 = 0; ks2 < 4; ks2++) {
            uint32_t a[4];
            a[0] = Pw[lr * 36 + ks2 * 8 + lc];
            a[1] = Pw[(lr + 8) * 36 + ks2 * 8 + lc];
            a[2] = Pw[lr * 36 + ks2 * 8 + lc + 4];
            a[3] = Pw[(lr + 8) * 36 + ks2 * 8 + lc + 4];
#pragma unroll
            for (int nt = 0; nt < 16; nt++) {
                uint32_t bf[2];
                *(uint2*)bf = *(const uint2*)&VB[(nt * 4 + ks2) * 64 + lid * 2];
                mma_f16(o[nt], a, bf);
            }
        }
        __syncthreads();   // protect KV stage before re-issue
    }

    // ---- epilogue: write out-proj A-fragments (g_of) directly ----
    // m = b*2048 + row, k = h*128 + col; A-frag u32 packs (k, k+1).
    const float inv0 = 1.0f / l0;
    const float inv1 = 1.0f / l1;
    const int mbp = b * 16 + (qb >> 1);
    const int gm  = (qb & 1) * 4 + wid;
#pragma unroll
    for (int nt = 0; nt < 16; nt++) {
        const int ch   = h * 2 + (nt >> 3);
        const int ks   = (nt & 7) >> 1;
        const int reg0 = (nt & 1) * 2;
        const size_t base = ((size_t)(mbp * NCH2) + ch) * 4096
                          + (gm * 4 + ks) * 128 + (lr * 4 + lc) * 4 + reg0;
        *(uint2*)&g_of[base] = make_uint2(
            pack_h2(o[nt][0] * inv0, o[nt][1] * inv0),    // row0 (r>>3 == 0)
            pack_h2(o[nt][2] * inv1, o[nt][3] * inv1));   // row1 (r>>3 == 1)
    }
}

// ---------------------------------------------------------------------------
// Launch
// ---------------------------------------------------------------------------
extern "C" void kernel_launch(void* const* d_in, const int* in_sizes, int n_in,
                              void* d_out, int out_size)
{
    const float* x    = (const float*)d_in[0];
    const float* Wqkv = (const float*)d_in[1];
    const float* Wout = (const float*)d_in[2];
    float* out = (float*)d_out;

    cudaFuncSetAttribute((const void*)gemm_h<1, 6>,
                         cudaFuncAttributeMaxDynamicSharedMemorySize, GF_SMEM_MAX);
    cudaFuncSetAttribute((const void*)gemm_h<0, 8>,
                         cudaFuncAttributeMaxDynamicSharedMemorySize, GF_SMEM_MAX);
    cudaFuncSetAttribute((const void*)flash_attn_v5,
                         cudaFuncAttributeMaxDynamicSharedMemorySize, ATT_SMEM);

    uint32_t *xf, *of, *wqf, *wof;
    cudaGetSymbolAddress((void**)&xf,  g_xf);
    cudaGetSymbolAddress((void**)&of,  g_of);
    cudaGetSymbolAddress((void**)&wqf, g_wqf);
    cudaGetSymbolAddress((void**)&wof, g_wof);

    // Pre-convert GEMM operands into fp16 fragment layouts
    conv_A<<<dim3(NCH2, 32), 256>>>(x,    xf);
    conv_B<<<dim3(NCH2, 48), 256>>>(Wqkv, wqf);
    conv_B<<<dim3(NCH2, 16), 256>>>(Wout, wof);

    // Stage 1: QKV projection, 128x192 tiles (1024 CTAs -> 98.9% wave eff)
    gemm_h<1, 6><<<dim3(32, 32), 256, 4 * (4096 + 3 * 2048) * 4>>>(xf, wqf, nullptr);

    // Stage 2: flash attention; epilogue emits out-proj A-fragments
    flash_attn_v5<<<dim3(32, BATCH * NHEADS), 128, ATT_SMEM>>>();

    // Stage 3: output projection (reads g_of directly)
    gemm_h<0, 8><<<dim3(8, 32), 256, GF_SMEM_MAX>>>(of, wof, out);
}

// round 11
// speedup vs baseline: 2.5560x; 1.0221x over previous
#include <cuda_runtime.h>
#include <cuda_fp16.h>
#include <cstdint>

// Problem constants
#define BATCH   2
#define SEQ     2048
#define DMODEL  2048
#define NHEADS  16
#define DHEAD   128

#define KC2  64                    // K elems per GEMM chunk
#define NCH2 32                    // chunks (K = 2048)

// ---------------------------------------------------------------------------
// Scratch (alloc-free: __device__ globals)
// ---------------------------------------------------------------------------
__device__ __align__(128) uint32_t g_xf [(size_t)32 * NCH2 * 4096];  // x     [4096,2048]
__device__ __align__(128) uint32_t g_of [(size_t)32 * NCH2 * 4096];  // attn out
__device__ __align__(128) uint32_t g_wqf[(size_t)48 * NCH2 * 4096];  // W_qkv [6144,2048]
__device__ __align__(128) uint32_t g_wof[(size_t)16 * NCH2 * 4096];  // W_out [2048,2048]

__device__ __align__(128) uint32_t g_Qf[(size_t)32 * 32 * 4096];
__device__ __align__(128) uint32_t g_Kf[(size_t)32 * 32 * 4096];
__device__ __align__(128) uint32_t g_Vf[(size_t)32 * 32 * 4096];

__device__ __forceinline__ uint32_t pack_h2(float lo, float hi) {
    __half2 h = __floats2half2_rn(lo, hi);
    return *reinterpret_cast<uint32_t*>(&h);
}

__device__ __forceinline__ void mma_f16(float* d, const uint32_t* a, const uint32_t* b) {
    asm volatile(
        "mma.sync.aligned.m16n8k16.row.col.f32.f16.f16.f32 "
        "{%0,%1,%2,%3}, {%4,%5,%6,%7}, {%8,%9}, {%0,%1,%2,%3};"
        : "+f"(d[0]), "+f"(d[1]), "+f"(d[2]), "+f"(d[3])
        : "r"(a[0]), "r"(a[1]), "r"(a[2]), "r"(a[3]), "r"(b[0]), "r"(b[1]));
}

__device__ __forceinline__ void cpa16(uint32_t dst, const void* src) {
    asm volatile("cp.async.cg.shared.global [%0], [%1], 16;"
                 :: "r"(dst), "l"(src) : "memory");
}
#define CPA_COMMIT() asm volatile("cp.async.commit_group;" ::: "memory")
#define CPA_WAIT(n)  asm volatile("cp.async.wait_group %0;" :: "n"(n) : "memory")

__device__ __forceinline__ uint32_t smem_u32(const void* p) {
    uint32_t a;
    asm("{ .reg .u64 t; cvta.to.shared.u64 t, %1; cvt.u32.u64 %0, t; }"
        : "=r"(a) : "l"(p));
    return a;
}

// Fragment index helpers (element (s,d) of head-batch bh)
__device__ __forceinline__ size_t qf_u32(int bh, int s, int d) {
    return (size_t)((bh * 32 + (s >> 6)) * 32 + (d >> 4) * 4 + ((s >> 4) & 3)) * 128
         + (((s & 7) * 4 + ((d & 7) >> 1)) << 2) + (((d >> 3) & 1) << 1) + ((s >> 3) & 1);
}
__device__ __forceinline__ size_t kf_u32(int bh, int s, int d) {
    return (size_t)((bh * 32 + (s >> 6)) * 64 + (d >> 4) * 8 + ((s >> 3) & 7)) * 64
         + (((s & 7) * 4 + ((d & 7) >> 1)) << 1) + ((d >> 3) & 1);
}
__device__ __forceinline__ size_t vf_u16(int bh, int s, int d) {
    return ((size_t)((bh * 32 + (s >> 6)) * 64 + (d >> 3) * 4 + ((s >> 4) & 3)) * 64
         + (((d & 7) * 4 + ((s & 7) >> 1)) << 1) + ((s >> 3) & 1)) * 2 + (s & 1);
}

// ---------------------------------------------------------------------------
// Fused conversion kernel: fp32 row-major -> fp16 fragment layouts.
// blocks [0,1024): x -> g_xf (A-frag); [1024,2560): W_qkv -> g_wqf (B-frag);
// [2560,3072): W_out -> g_wof (B-frag).
// ---------------------------------------------------------------------------
__device__ __forceinline__ void conv_A_body(
    const float* __restrict__ src, uint32_t* __restrict__ dst,
    int ch, int mb, int tid, float (*s)[65])
{
    const float* base = src + (size_t)mb * 128 * DMODEL + ch * KC2;
#pragma unroll
    for (int i = 0; i < 8; i++) {
        const int idx = tid + i * 256;
        const int row = idx >> 4, c4 = idx & 15;
        float4 v = *(const float4*)(base + (size_t)row * DMODEL + c4 * 4);
        s[row][c4 * 4 + 0] = v.x; s[row][c4 * 4 + 1] = v.y;
        s[row][c4 * 4 + 2] = v.z; s[row][c4 * 4 + 3] = v.w;
    }
    __syncthreads();
    uint32_t* out = dst + ((size_t)mb * NCH2 + ch) * 4096;
#pragma unroll
    for (int i = 0; i < 16; i++) {
        const int u = tid + i * 256;
        const int blk = u >> 7, rem = u & 127;
        const int lane = rem >> 2, reg = rem & 3;
        const int gm = blk >> 2, ks = blk & 3;
        const int r = (reg & 1) * 8 + (lane >> 2);
        const int c = (reg >> 1) * 8 + (lane & 3) * 2;
        const int k = ks * 16 + c;
        out[u] = pack_h2(s[gm * 16 + r][k], s[gm * 16 + r][k + 1]);
    }
}

__device__ __forceinline__ void conv_B_body(
    const float* __restrict__ src, uint32_t* __restrict__ dst,
    int ch, int nb, int tid, float (*s)[65])
{
    const float* base = src + (size_t)nb * 128 * DMODEL + ch * KC2;
#pragma unroll
    for (int i = 0; i < 8; i++) {
        const int idx = tid + i * 256;
        const int row = idx >> 4, c4 = idx & 15;
        float4 v = *(const float4*)(base + (size_t)row * DMODEL + c4 * 4);
        s[row][c4 * 4 + 0] = v.x; s[row][c4 * 4 + 1] = v.y;
        s[row][c4 * 4 + 2] = v.z; s[row][c4 * 4 + 3] = v.w;
    }
    __syncthreads();
    uint32_t* out = dst + ((size_t)nb * NCH2 + ch) * 4096;
#pragma unroll
    for (int i = 0; i < 16; i++) {
        const int u = tid + i * 256;
        const int blk = u >> 6, rem = u & 63;
        const int lane = rem >> 1, reg = rem & 1;
        const int gn = blk >> 2, ks = blk & 3;
        const int n = lane >> 2, tig = lane & 3;
        const int k = ks * 16 + reg * 8 + tig * 2;
        out[u] = pack_h2(s[gn * 8 + n][k], s[gn * 8 + n][k + 1]);
    }
}

__global__ void __launch_bounds__(256)
conv_all(const float* __restrict__ x, const float* __restrict__ wq,
         const float* __restrict__ wo)
{
    __shared__ float s[128][65];
    const int bid = blockIdx.x;
    const int tid = threadIdx.x;
    if (bid < 1024) {
        conv_A_body(x,  g_xf,  bid & 31, bid >> 5, tid, s);
    } else if (bid < 2560) {
        const int b2 = bid - 1024;
        conv_B_body(wq, g_wqf, b2 & 31, b2 >> 5, tid, s);
    } else {
        const int b2 = bid - 2560;
        conv_B_body(wo, g_wof, b2 & 31, b2 >> 5, tid, s);
    }
}

// ---------------------------------------------------------------------------
// QKV GEMM: 128-thread CTAs, tile 128(m) x 96(n), 4 warps (2m x 2n),
// warp tile 64x48. 3-stage cp.async ring (28KB/stage -> 84KB -> 2 CTAs/SM),
// ONE barrier per chunk (prefetch issued AFTER compute; writer stage
// (c+2)%3 disjoint from laggard readers at c%3).
// Epilogue emits Q/K/V fp16 fragments (per-element head/tensor decode).
// ---------------------------------------------------------------------------
#define QSTG     7168                       // u32 per stage (A 4096 + B 3072)
#define QKV_SMEM (3 * QSTG * 4)             // 86016 bytes

__global__ void __launch_bounds__(128)
gemm_qkv(const uint32_t* __restrict__ Af, const uint32_t* __restrict__ Bf)
{
    extern __shared__ uint32_t us[];
    const int tid = threadIdx.x;
    const int wid = tid >> 5;
    const int lid = tid & 31;
    const int wm  = wid & 1;                // m half (64 rows)
    const int wn  = wid >> 1;               // n half (48 cols)
    const int mb  = blockIdx.y;
    const int n0  = blockIdx.x * 96;
    const uint32_t sb = smem_u32(us);

    float acc[4][6][4];
#pragma unroll
    for (int i = 0; i < 4; i++)
#pragma unroll
        for (int j = 0; j < 6; j++)
#pragma unroll
            for (int v = 0; v < 4; v++) acc[i][j][v] = 0.0f;

    auto issue = [&](int c, int st) {
        const uint32_t sA = sb + st * (QSTG * 4);
        const uint32_t sB = sA + 16384;
        const uint32_t* gA = Af + ((size_t)mb * NCH2 + c) * 4096;
#pragma unroll
        for (int i = 0; i < 8; i++) {
            const int o = tid + i * 128;
            cpa16(sA + o * 16, gA + (size_t)o * 4);
        }
#pragma unroll
        for (int i = 0; i < 6; i++) {
            const int idx = tid + i * 128;            // 0..767
            const int g   = idx >> 6;                 // 8-col group 0..11
            const int w64 = idx & 63;
            const int col = n0 + g * 8;
            const uint32_t* gB = Bf + ((size_t)(col >> 7) * NCH2 + c) * 4096
                                    + ((col >> 3) & 15) * 256 + w64 * 4;
            cpa16(sB + (g * 256 + w64 * 4) * 4, gB);
        }
        CPA_COMMIT();
    };

    issue(0, 0);
    issue(1, 1);

    for (int c = 0; c < NCH2; ++c) {
        if (c < NCH2 - 1) { CPA_WAIT(1); }
        else              { CPA_WAIT(0); }
        __syncthreads();

        const uint32_t* uA = us + (c % 3) * QSTG;
        const uint32_t* uB = uA + 4096;
#pragma unroll
        for (int ks = 0; ks < 4; ks++) {
            uint4 a[4];
            uint32_t b[6][2];
#pragma unroll
            for (int mt = 0; mt < 4; mt++)
                a[mt] = *(const uint4*)&uA[(((wm * 4 + mt) * 4 + ks) * 32 + lid) * 4];
#pragma unroll
            for (int nt = 0; nt < 6; nt++) {
                const int g = wn * 6 + nt;
                *(uint2*)b[nt] = *(const uint2*)&uB[g * 256 + ks * 64 + lid * 2];
            }
#pragma unroll
            for (int mt = 0; mt < 4; mt++)
#pragma unroll
                for (int nt = 0; nt < 6; nt++)
                    mma_f16(acc[mt][nt], (const uint32_t*)&a[mt], b[nt]);
        }

        if (c + 2 < NCH2) issue(c + 2, (c + 2) % 3);
    }

    // ---- epilogue: per-element Q/K/V fragment scatter ----
    const int lr  = lid >> 2;
    const int lc2 = (lid & 3) * 2;
    const int m0  = mb * 128;
    __half* vh = (__half*)g_Vf;
#pragma unroll
    for (int mt = 0; mt < 4; mt++) {
        const int m = m0 + wm * 64 + mt * 16 + lr;
#pragma unroll
        for (int nt = 0; nt < 6; nt++) {
            const int cg = n0 + wn * 48 + nt * 8 + lc2;
            const int t  = cg >> 11;               // 0=Q,1=K,2=V
            const int h  = (cg >> 7) & (NHEADS - 1);
            const int d  = cg & (DHEAD - 1);
            const int b  = m >> 11;
            const int s  = m & (SEQ - 1);
            const int bh = b * NHEADS + h;
            if (t == 0) {
                g_Qf[qf_u32(bh, s,     d)] = pack_h2(acc[mt][nt][0], acc[mt][nt][1]);
                g_Qf[qf_u32(bh, s + 8, d)] = pack_h2(acc[mt][nt][2], acc[mt][nt][3]);
            } else if (t == 1) {
                g_Kf[kf_u32(bh, s,     d)] = pack_h2(acc[mt][nt][0], acc[mt][nt][1]);
                g_Kf[kf_u32(bh, s + 8, d)] = pack_h2(acc[mt][nt][2], acc[mt][nt][3]);
            } else {
                vh[vf_u16(bh, s,     d    )] = __float2half_rn(acc[mt][nt][0]);
                vh[vf_u16(bh, s,     d + 1)] = __float2half_rn(acc[mt][nt][1]);
                vh[vf_u16(bh, s + 8, d    )] = __float2half_rn(acc[mt][nt][2]);
                vh[vf_u16(bh, s + 8, d + 1)] = __float2half_rn(acc[mt][nt][3]);
            }
        }
    }
}

// ---------------------------------------------------------------------------
// Output-projection GEMM (round-10 structure, MODE 0, NNT=8, 256 threads).
// ---------------------------------------------------------------------------
#define GF_SMEM_MAX (4 * (4096 + 4 * 2048) * 4)    // 196608 bytes

__global__ void __launch_bounds__(256)
gemm_out(const uint32_t* __restrict__ Af, const uint32_t* __restrict__ Bf,
         float* __restrict__ C)
{
    constexpr int NNT   = 8;
    constexpr int NBT64 = NNT / 2;
    constexpr int STG   = 4096 + NBT64 * 2048;

    extern __shared__ uint32_t us[];
    const int tid = threadIdx.x;
    const int wid = tid >> 5;
    const int lid = tid & 31;
    const int wm  = wid & 1;
    const int wn  = wid >> 1;
    const int mb  = blockIdx.y;
    const int n0  = blockIdx.x * (NNT * 32);
    const uint32_t sb = smem_u32(us);

    float acc[4][NNT][4];
#pragma unroll
    for (int i = 0; i < 4; i++)
#pragma unroll
        for (int j = 0; j < NNT; j++)
#pragma unroll
            for (int v = 0; v < 4; v++) acc[i][j][v] = 0.0f;

    auto issue = [&](int c, int st) {
        const uint32_t sA = sb + st * (STG * 4);
        const uint32_t sB = sA + 16384;
        const uint32_t* gA = Af + ((size_t)mb * NCH2 + c) * 4096;
#pragma unroll
        for (int i = 0; i < 4; i++) {
            const int o = tid + i * 256;
            cpa16(sA + o * 16, gA + (size_t)o * 4);
        }
#pragma unroll
        for (int j = 0; j < NBT64; j++) {
            const int c64 = (n0 >> 6) + j;
            const uint32_t* gB = Bf + ((size_t)(c64 >> 1) * NCH2 + c) * 4096
                                    + (c64 & 1) * 2048;
#pragma unroll
            for (int i = 0; i < 2; i++) {
                const int o = tid + i * 256;
                cpa16(sB + j * 8192 + o * 16, gB + (size_t)o * 4);
            }
        }
        CPA_COMMIT();
    };

    issue(0, 0);
    issue(1, 1);

    for (int c = 0; c < NCH2; ++c) {
        const int st = c & 3;
        if (c + 2 < NCH2)      { issue(c + 2, (c + 2) & 3); CPA_WAIT(2); }
        else if (c + 1 < NCH2) { CPA_WAIT(1); }
        else                   { CPA_WAIT(0); }
        __syncthreads();

        const uint32_t* uA = us + st * STG;
        const uint32_t* uB = uA + 4096;
#pragma unroll
        for (int ks = 0; ks < 4; ks++) {
            uint4 a[4];
            uint32_t b[NNT][2];
#pragma unroll
            for (int mt = 0; mt < 4; mt++)
                a[mt] = *(const uint4*)&uA[(((wm * 4 + mt) * 4 + ks) * 32 + lid) * 4];
#pragma unroll
            for (int nt = 0; nt < NNT; nt++) {
                const int col = wn * (NNT * 8) + nt * 8;
                *(uint2*)b[nt] = *(const uint2*)
                    &uB[(col >> 6) * 2048 + ((((col >> 3) & 7) * 4 + ks) * 64) + lid * 2];
            }
#pragma unroll
            for (int mt = 0; mt < 4; mt++)
#pragma unroll
                for (int nt = 0; nt < NNT; nt++)
                    mma_f16(acc[mt][nt], (const uint32_t*)&a[mt], b[nt]);
        }
    }

    const int lr  = lid >> 2;
    const int lc2 = (lid & 3) * 2;
    const int m0  = mb * 128;
#pragma unroll
    for (int mt = 0; mt < 4; mt++) {
        const int m = m0 + wm * 64 + mt * 16 + lr;
#pragma unroll
        for (int nt = 0; nt < NNT; nt++) {
            const int cg = n0 + wn * (NNT * 8) + nt * 8 + lc2;
            float* dst = C + (size_t)m * DMODEL + cg;
            *(float2*)dst                         = make_float2(acc[mt][nt][0], acc[mt][nt][1]);
            *(float2*)(dst + (size_t)8 * DMODEL)  = make_float2(acc[mt][nt][2], acc[mt][nt][3]);
        }
    }
}

// ---------------------------------------------------------------------------
// Flash attention v6: 128 threads, 64-row Q tiles, Q in registers,
// 3-stage cp.async KV ring with ONE barrier per iteration (issue-at-end).
// Epilogue writes out-proj A-fragments (g_of) directly.
// ---------------------------------------------------------------------------
#define KV_U32   4096                              // one K (or V) tile: 16 KB
#define ATT_SMEM ((3 * 2 * KV_U32 + 4 * 576) * 4)  // 107520 bytes

__global__ void __launch_bounds__(128)
flash_attn_v6()
{
    extern __shared__ uint32_t sm32[];
    const int tid = threadIdx.x;
    const int wid = tid >> 5;
    const int lid = tid & 31;
    const int qb  = gridDim.x - 1 - blockIdx.x;    // big tiles first
    const int bh  = blockIdx.y;
    const int b   = bh >> 4;
    const int h   = bh & (NHEADS - 1);
    uint32_t* Pw = sm32 + 3 * 2 * KV_U32 + wid * 576;
    const uint32_t sb = smem_u32(sm32);

    // ---- Q fragments into registers ----
    uint32_t q[8][4];
    {
        const uint4* qg = (const uint4*)(g_Qf + (size_t)(bh * 32 + qb) * 4096);
#pragma unroll
        for (int kt = 0; kt < 8; kt++) {
            uint4 v = __ldg(&qg[(kt * 4 + wid) * 32 + lid]);
            q[kt][0] = v.x; q[kt][1] = v.y; q[kt][2] = v.z; q[kt][3] = v.w;
        }
    }

    auto issueKV = [&](int kb, int st) {
        const uint4* gk = (const uint4*)(g_Kf + (size_t)(bh * 32 + kb) * KV_U32);
        const uint4* gv = (const uint4*)(g_Vf + (size_t)(bh * 32 + kb) * KV_U32);
        const uint32_t base = sb + st * (2 * KV_U32 * 4);
#pragma unroll
        for (int i = 0; i < 8; i++)
            cpa16(base + (tid + i * 128) * 16, gk + tid + i * 128);
#pragma unroll
        for (int i = 0; i < 8; i++)
            cpa16(base + KV_U32 * 4 + (tid + i * 128) * 16, gv + tid + i * 128);
        CPA_COMMIT();
    };

    float o[16][4];
#pragma unroll
    for (int nt = 0; nt < 16; nt++)
#pragma unroll
        for (int v = 0; v < 4; v++) o[nt][v] = 0.0f;

    float mx0 = -1e30f, mx1 = -1e30f, l0 = 0.0f, l1 = 0.0f;
    const float scale = 0.08838834764831845f;      // 1/sqrt(128)
    const int lr = lid >> 2;
    const int lc = lid & 3;
    const int q0 = qb * 64;
    const int row0 = q0 + wid * 16 + lr;
    const int row1 = row0 + 8;

    issueKV(0, 0);
    if (qb >= 1) issueKV(1, 1);

    for (int kb = 0; kb <= qb; kb++) {
        if (kb < qb) { CPA_WAIT(1); }
        else         { CPA_WAIT(0); }
        __syncthreads();

        const uint32_t* KB = sm32 + (kb % 3) * 2 * KV_U32;
        const uint32_t* VB = KB + KV_U32;

        float s[8][4];
#pragma unroll
        for (int nt = 0; nt < 8; nt++)
#pragma unroll
            for (int v = 0; v < 4; v++) s[nt][v] = 0.0f;

#pragma unroll
        for (int kt = 0; kt < 8; kt++)
#pragma unroll
            for (int nt = 0; nt < 8; nt++) {
                uint32_t bf[2];
                *(uint2*)bf = *(const uint2*)&KB[(kt * 8 + nt) * 64 + lid * 2];
                mma_f16(s[nt], q[kt], bf);
            }

        const bool domask = (kb == qb);
        const int k0 = kb * 64;
        float ml0 = -1e30f, ml1 = -1e30f;
#pragma unroll
        for (int nt = 0; nt < 8; nt++) {
            const int c0 = k0 + nt * 8 + lc * 2;
            s[nt][0] *= scale; s[nt][1] *= scale;
            s[nt][2] *= scale; s[nt][3] *= scale;
            if (domask) {
                if (c0     > row0) s[nt][0] = -1e30f;
                if (c0 + 1 > row0) s[nt][1] = -1e30f;
                if (c0     > row1) s[nt][2] = -1e30f;
                if (c0 + 1 > row1) s[nt][3] = -1e30f;
            }
            ml0 = fmaxf(ml0, fmaxf(s[nt][0], s[nt][1]));
            ml1 = fmaxf(ml1, fmaxf(s[nt][2], s[nt][3]));
        }
        ml0 = fmaxf(ml0, __shfl_xor_sync(0xffffffffu, ml0, 1));
        ml0 = fmaxf(ml0, __shfl_xor_sync(0xffffffffu, ml0, 2));
        ml1 = fmaxf(ml1, __shfl_xor_sync(0xffffffffu, ml1, 1));
        ml1 = fmaxf(ml1, __shfl_xor_sync(0xffffffffu, ml1, 2));

        const float mn0 = fmaxf(mx0, ml0);
        const float mn1 = fmaxf(mx1, ml1);
        const float f0 = __expf(mx0 - mn0);
        const float f1 = __expf(mx1 - mn1);
        mx0 = mn0; mx1 = mn1;

        float rs0 = 0.0f, rs1 = 0.0f;
#pragma unroll
        for (int nt = 0; nt < 8; nt++) {
            s[nt][0] = __expf(s[nt][0] - mn0);
            s[nt][1] = __expf(s[nt][1] - mn0);
            s[nt][2] = __expf(s[nt][2] - mn1);
            s[nt][3] = __expf(s[nt][3] - mn1);
            rs0 += s[nt][0] + s[nt][1];
            rs1 += s[nt][2] + s[nt][3];
        }
        rs0 += __shfl_xor_sync(0xffffffffu, rs0, 1);
        rs0 += __shfl_xor_sync(0xffffffffu, rs0, 2);
        rs1 += __shfl_xor_sync(0xffffffffu, rs1, 1);
        rs1 += __shfl_xor_sync(0xffffffffu, rs1, 2);
        l0 = l0 * f0 + rs0;
        l1 = l1 * f1 + rs1;

#pragma unroll
        for (int nt = 0; nt < 16; nt++) {
            o[nt][0] *= f0; o[nt][1] *= f0;
            o[nt][2] *= f1; o[nt][3] *= f1;
        }

#pragma unroll
        for (int nt = 0; nt < 8; nt++) {
            Pw[lr * 36 + nt * 4 + lc]       = pack_h2(s[nt][0], s[nt][1]);
            Pw[(lr + 8) * 36 + nt * 4 + lc] = pack_h2(s[nt][2], s[nt][3]);
        }
        __syncwarp();

#pragma unroll
        for (int ks2 = 0; ks2 < 4; ks2++) {
            uint32_t a[4];
            a[0] = Pw[lr * 36 + ks2 * 8 + lc];
            a[1] = Pw[(lr + 8) * 36 + ks2 * 8 + lc];
            a[2] = Pw[lr * 36 + ks2 * 8 + lc + 4];
            a[3] = Pw[(lr + 8) * 36 + ks2 * 8 + lc + 4];
#pragma unroll
            for (int nt = 0; nt < 16; nt++) {
                uint32_t bf[2];
                *(uint2*)bf = *(const uint2*)&VB[(nt * 4 + ks2) * 64 + lid * 2];
                mma_f16(o[nt], a, bf);
            }
        }

        // prefetch AFTER compute: stage (kb+2)%3 disjoint from any laggard's
        // reads of stage kb%3 (single barrier bounds skew to one iteration)
        if (kb + 2 <= qb) issueKV(kb + 2, (kb + 2) % 3);
    }

    // ---- epilogue: out-proj A-fragments (g_of) ----
    const float inv0 = 1.0f / l0;
    const float inv1 = 1.0f / l1;
    const int mbp = b * 16 + (qb >> 1);
    const int gm  = (qb & 1) * 4 + wid;
#pragma unroll
    for (int nt = 0; nt < 16; nt++) {
        const int ch   = h * 2 + (nt >> 3);
        const int ks   = (nt & 7) >> 1;
        const int reg0 = (nt & 1) * 2;
        const size_t base = ((size_t)(mbp * NCH2) + ch) * 4096
                          + (gm * 4 + ks) * 128 + (lr * 4 + lc) * 4 + reg0;
        *(uint2*)&g_of[base] = make_uint2(
            pack_h2(o[nt][0] * inv0, o[nt][1] * inv0),
            pack_h2(o[nt][2] * inv1, o[nt][3] * inv1));
    }
}

// ---------------------------------------------------------------------------
// Launch
// ---------------------------------------------------------------------------
extern "C" void kernel_launch(void* const* d_in, const int* in_sizes, int n_in,
                              void* d_out, int out_size)
{
    const float* x    = (const float*)d_in[0];
    const float* Wqkv = (const float*)d_in[1];
    const float* Wout = (const float*)d_in[2];
    float* out = (float*)d_out;

    cudaFuncSetAttribute((const void*)gemm_qkv,
                         cudaFuncAttributeMaxDynamicSharedMemorySize, QKV_SMEM);
    cudaFuncSetAttribute((const void*)gemm_out,
                         cudaFuncAttributeMaxDynamicSharedMemorySize, GF_SMEM_MAX);
    cudaFuncSetAttribute((const void*)flash_attn_v6,
                         cudaFuncAttributeMaxDynamicSharedMemorySize, ATT_SMEM);

    uint32_t *xf, *of, *wqf, *wof;
    cudaGetSymbolAddress((void**)&xf,  g_xf);
    cudaGetSymbolAddress((void**)&of,  g_of);
    cudaGetSymbolAddress((void**)&wqf, g_wqf);
    cudaGetSymbolAddress((void**)&wof, g_wof);

    // Stage 0: all operand conversions in one launch
    conv_all<<<3072, 256>>>(x, Wqkv, Wout);

    // Stage 1: QKV projection (128x96 tiles, 2 CTAs/SM)
    gemm_qkv<<<dim3(64, 32), 128, QKV_SMEM>>>(xf, wqf);

    // Stage 2: flash attention (3-stage ring, 1 barrier/iter)
    flash_attn_v6<<<dim3(32, BATCH * NHEADS), 128, ATT_SMEM>>>();

    // Stage 3: output projection
    gemm_out<<<dim3(8, 32), 256, GF_SMEM_MAX>>>(of, wof, out);
}

// round 12
// speedup vs baseline: 2.5705x; 1.0057x over previous
#include <cuda_runtime.h>
#include <cuda_fp16.h>
#include <cstdint>

// Problem constants
#define BATCH   2
#define SEQ     2048
#define DMODEL  2048
#define NHEADS  16
#define DHEAD   128

#define KC2  64                    // K elems per GEMM chunk
#define NCH2 32                    // chunks (K = 2048)

// ---------------------------------------------------------------------------
// Scratch (alloc-free: __device__ globals)
// ---------------------------------------------------------------------------
__device__ __align__(128) uint32_t g_xf [(size_t)32 * NCH2 * 4096];  // x     [4096,2048]
__device__ __align__(128) uint32_t g_of [(size_t)32 * NCH2 * 4096];  // attn out
__device__ __align__(128) uint32_t g_wqf[(size_t)48 * NCH2 * 4096];  // W_qkv [6144,2048]
__device__ __align__(128) uint32_t g_wof[(size_t)16 * NCH2 * 4096];  // W_out [2048,2048]

__device__ __align__(128) uint32_t g_Qf[(size_t)32 * 32 * 4096];
__device__ __align__(128) uint32_t g_Kf[(size_t)32 * 32 * 4096];
__device__ __align__(128) uint32_t g_Vf[(size_t)32 * 32 * 4096];

__device__ __forceinline__ uint32_t pack_h2(float lo, float hi) {
    __half2 h = __floats2half2_rn(lo, hi);
    return *reinterpret_cast<uint32_t*>(&h);
}

__device__ __forceinline__ void mma_f16(float* d, const uint32_t* a, const uint32_t* b) {
    asm volatile(
        "mma.sync.aligned.m16n8k16.row.col.f32.f16.f16.f32 "
        "{%0,%1,%2,%3}, {%4,%5,%6,%7}, {%8,%9}, {%0,%1,%2,%3};"
        : "+f"(d[0]), "+f"(d[1]), "+f"(d[2]), "+f"(d[3])
        : "r"(a[0]), "r"(a[1]), "r"(a[2]), "r"(a[3]), "r"(b[0]), "r"(b[1]));
}

__device__ __forceinline__ void cpa16(uint32_t dst, const void* src) {
    asm volatile("cp.async.cg.shared.global [%0], [%1], 16;"
                 :: "r"(dst), "l"(src) : "memory");
}
#define CPA_COMMIT() asm volatile("cp.async.commit_group;" ::: "memory")
#define CPA_WAIT(n)  asm volatile("cp.async.wait_group %0;" :: "n"(n) : "memory")

__device__ __forceinline__ uint32_t smem_u32(const void* p) {
    uint32_t a;
    asm("{ .reg .u64 t; cvta.to.shared.u64 t, %1; cvt.u32.u64 %0, t; }"
        : "=r"(a) : "l"(p));
    return a;
}

// Fragment index helpers (element (s,d) of head-batch bh)
__device__ __forceinline__ size_t qf_u32(int bh, int s, int d) {
    return (size_t)((bh * 32 + (s >> 6)) * 32 + (d >> 4) * 4 + ((s >> 4) & 3)) * 128
         + (((s & 7) * 4 + ((d & 7) >> 1)) << 2) + (((d >> 3) & 1) << 1) + ((s >> 3) & 1);
}
__device__ __forceinline__ size_t kf_u32(int bh, int s, int d) {
    return (size_t)((bh * 32 + (s >> 6)) * 64 + (d >> 4) * 8 + ((s >> 3) & 7)) * 64
         + (((s & 7) * 4 + ((d & 7) >> 1)) << 1) + ((d >> 3) & 1);
}
__device__ __forceinline__ size_t vf_u16(int bh, int s, int d) {
    return ((size_t)((bh * 32 + (s >> 6)) * 64 + (d >> 3) * 4 + ((s >> 4) & 3)) * 64
         + (((d & 7) * 4 + ((s & 7) >> 1)) << 1) + ((s >> 3) & 1)) * 2 + (s & 1);
}

// ---------------------------------------------------------------------------
// Fused conversion kernel: fp32 row-major -> fp16 fragment layouts.
// ---------------------------------------------------------------------------
__device__ __forceinline__ void conv_A_body(
    const float* __restrict__ src, uint32_t* __restrict__ dst,
    int ch, int mb, int tid, float (*s)[65])
{
    const float* base = src + (size_t)mb * 128 * DMODEL + ch * KC2;
#pragma unroll
    for (int i = 0; i < 8; i++) {
        const int idx = tid + i * 256;
        const int row = idx >> 4, c4 = idx & 15;
        float4 v = *(const float4*)(base + (size_t)row * DMODEL + c4 * 4);
        s[row][c4 * 4 + 0] = v.x; s[row][c4 * 4 + 1] = v.y;
        s[row][c4 * 4 + 2] = v.z; s[row][c4 * 4 + 3] = v.w;
    }
    __syncthreads();
    uint32_t* out = dst + ((size_t)mb * NCH2 + ch) * 4096;
#pragma unroll
    for (int i = 0; i < 16; i++) {
        const int u = tid + i * 256;
        const int blk = u >> 7, rem = u & 127;
        const int lane = rem >> 2, reg = rem & 3;
        const int gm = blk >> 2, ks = blk & 3;
        const int r = (reg & 1) * 8 + (lane >> 2);
        const int c = (reg >> 1) * 8 + (lane & 3) * 2;
        const int k = ks * 16 + c;
        out[u] = pack_h2(s[gm * 16 + r][k], s[gm * 16 + r][k + 1]);
    }
}

__device__ __forceinline__ void conv_B_body(
    const float* __restrict__ src, uint32_t* __restrict__ dst,
    int ch, int nb, int tid, float (*s)[65])
{
    const float* base = src + (size_t)nb * 128 * DMODEL + ch * KC2;
#pragma unroll
    for (int i = 0; i < 8; i++) {
        const int idx = tid + i * 256;
        const int row = idx >> 4, c4 = idx & 15;
        float4 v = *(const float4*)(base + (size_t)row * DMODEL + c4 * 4);
        s[row][c4 * 4 + 0] = v.x; s[row][c4 * 4 + 1] = v.y;
        s[row][c4 * 4 + 2] = v.z; s[row][c4 * 4 + 3] = v.w;
    }
    __syncthreads();
    uint32_t* out = dst + ((size_t)nb * NCH2 + ch) * 4096;
#pragma unroll
    for (int i = 0; i < 16; i++) {
        const int u = tid + i * 256;
        const int blk = u >> 6, rem = u & 63;
        const int lane = rem >> 1, reg = rem & 1;
        const int gn = blk >> 2, ks = blk & 3;
        const int n = lane >> 2, tig = lane & 3;
        const int k = ks * 16 + reg * 8 + tig * 2;
        out[u] = pack_h2(s[gn * 8 + n][k], s[gn * 8 + n][k + 1]);
    }
}

__global__ void __launch_bounds__(256)
conv_all(const float* __restrict__ x, const float* __restrict__ wq,
         const float* __restrict__ wo)
{
    __shared__ float s[128][65];
    const int bid = blockIdx.x;
    const int tid = threadIdx.x;
    if (bid < 1024) {
        conv_A_body(x,  g_xf,  bid & 31, bid >> 5, tid, s);
    } else if (bid < 2560) {
        const int b2 = bid - 1024;
        conv_B_body(wq, g_wqf, b2 & 31, b2 >> 5, tid, s);
    } else {
        const int b2 = bid - 2560;
        conv_B_body(wo, g_wof, b2 & 31, b2 >> 5, tid, s);
    }
}

// ---------------------------------------------------------------------------
// QKV GEMM (round-11): 128-thread CTAs, tile 128x96, 3-stage ring,
// ONE barrier per chunk. Epilogue emits Q/K/V fp16 fragments.
// ---------------------------------------------------------------------------
#define QSTG     7168
#define QKV_SMEM (3 * QSTG * 4)             // 86016 bytes

__global__ void __launch_bounds__(128)
gemm_qkv(const uint32_t* __restrict__ Af, const uint32_t* __restrict__ Bf)
{
    extern __shared__ uint32_t us[];
    const int tid = threadIdx.x;
    const int wid = tid >> 5;
    const int lid = tid & 31;
    const int wm  = wid & 1;
    const int wn  = wid >> 1;
    const int mb  = blockIdx.y;
    const int n0  = blockIdx.x * 96;
    const uint32_t sb = smem_u32(us);

    float acc[4][6][4];
#pragma unroll
    for (int i = 0; i < 4; i++)
#pragma unroll
        for (int j = 0; j < 6; j++)
#pragma unroll
            for (int v = 0; v < 4; v++) acc[i][j][v] = 0.0f;

    auto issue = [&](int c, int st) {
        const uint32_t sA = sb + st * (QSTG * 4);
        const uint32_t sB = sA + 16384;
        const uint32_t* gA = Af + ((size_t)mb * NCH2 + c) * 4096;
#pragma unroll
        for (int i = 0; i < 8; i++) {
            const int o = tid + i * 128;
            cpa16(sA + o * 16, gA + (size_t)o * 4);
        }
#pragma unroll
        for (int i = 0; i < 6; i++) {
            const int idx = tid + i * 128;
            const int g   = idx >> 6;
            const int w64 = idx & 63;
            const int col = n0 + g * 8;
            const uint32_t* gB = Bf + ((size_t)(col >> 7) * NCH2 + c) * 4096
                                    + ((col >> 3) & 15) * 256 + w64 * 4;
            cpa16(sB + (g * 256 + w64 * 4) * 4, gB);
        }
        CPA_COMMIT();
    };

    issue(0, 0);
    issue(1, 1);

    for (int c = 0; c < NCH2; ++c) {
        if (c < NCH2 - 1) { CPA_WAIT(1); }
        else              { CPA_WAIT(0); }
        __syncthreads();

        const uint32_t* uA = us + (c % 3) * QSTG;
        const uint32_t* uB = uA + 4096;
#pragma unroll
        for (int ks = 0; ks < 4; ks++) {
            uint4 a[4];
            uint32_t b[6][2];
#pragma unroll
            for (int mt = 0; mt < 4; mt++)
                a[mt] = *(const uint4*)&uA[(((wm * 4 + mt) * 4 + ks) * 32 + lid) * 4];
#pragma unroll
            for (int nt = 0; nt < 6; nt++) {
                const int g = wn * 6 + nt;
                *(uint2*)b[nt] = *(const uint2*)&uB[g * 256 + ks * 64 + lid * 2];
            }
#pragma unroll
            for (int mt = 0; mt < 4; mt++)
#pragma unroll
                for (int nt = 0; nt < 6; nt++)
                    mma_f16(acc[mt][nt], (const uint32_t*)&a[mt], b[nt]);
        }

        if (c + 2 < NCH2) issue(c + 2, (c + 2) % 3);
    }

    const int lr  = lid >> 2;
    const int lc2 = (lid & 3) * 2;
    const int m0  = mb * 128;
    __half* vh = (__half*)g_Vf;
#pragma unroll
    for (int mt = 0; mt < 4; mt++) {
        const int m = m0 + wm * 64 + mt * 16 + lr;
#pragma unroll
        for (int nt = 0; nt < 6; nt++) {
            const int cg = n0 + wn * 48 + nt * 8 + lc2;
            const int t  = cg >> 11;
            const int h  = (cg >> 7) & (NHEADS - 1);
            const int d  = cg & (DHEAD - 1);
            const int b  = m >> 11;
            const int s  = m & (SEQ - 1);
            const int bh = b * NHEADS + h;
            if (t == 0) {
                g_Qf[qf_u32(bh, s,     d)] = pack_h2(acc[mt][nt][0], acc[mt][nt][1]);
                g_Qf[qf_u32(bh, s + 8, d)] = pack_h2(acc[mt][nt][2], acc[mt][nt][3]);
            } else if (t == 1) {
                g_Kf[kf_u32(bh, s,     d)] = pack_h2(acc[mt][nt][0], acc[mt][nt][1]);
                g_Kf[kf_u32(bh, s + 8, d)] = pack_h2(acc[mt][nt][2], acc[mt][nt][3]);
            } else {
                vh[vf_u16(bh, s,     d    )] = __float2half_rn(acc[mt][nt][0]);
                vh[vf_u16(bh, s,     d + 1)] = __float2half_rn(acc[mt][nt][1]);
                vh[vf_u16(bh, s + 8, d    )] = __float2half_rn(acc[mt][nt][2]);
                vh[vf_u16(bh, s + 8, d + 1)] = __float2half_rn(acc[mt][nt][3]);
            }
        }
    }
}

// ---------------------------------------------------------------------------
// Output-projection GEMM v2: 128-thread CTAs, tile 128(m) x 128(n),
// 4 warps (2m x 2n), warp tile 64x64. 3-stage ring (32KB/stage -> 96KB
// -> 2 CTAs/SM), ONE barrier per chunk (issue-after-compute).
// ---------------------------------------------------------------------------
#define OSTG     8192                       // u32 per stage (A 4096 + B 4096)
#define OUT_SMEM (3 * OSTG * 4)             // 98304 bytes

__global__ void __launch_bounds__(128)
gemm_out(const uint32_t* __restrict__ Af, const uint32_t* __restrict__ Bf,
         float* __restrict__ C)
{
    extern __shared__ uint32_t us[];
    const int tid = threadIdx.x;
    const int wid = tid >> 5;
    const int lid = tid & 31;
    const int wm  = wid & 1;                // 64-row half
    const int wn  = wid >> 1;               // 64-col half
    const int mb  = blockIdx.y;
    const int nb  = blockIdx.x;             // 128-col tile
    const uint32_t sb = smem_u32(us);

    float acc[4][8][4];
#pragma unroll
    for (int i = 0; i < 4; i++)
#pragma unroll
        for (int j = 0; j < 8; j++)
#pragma unroll
            for (int v = 0; v < 4; v++) acc[i][j][v] = 0.0f;

    auto issue = [&](int c, int st) {
        const uint32_t sA = sb + st * (OSTG * 4);
        const uint32_t sB = sA + 16384;
        const uint32_t* gA = Af + ((size_t)mb * NCH2 + c) * 4096;
        const uint32_t* gB = Bf + ((size_t)nb * NCH2 + c) * 4096;
#pragma unroll
        for (int i = 0; i < 8; i++) {
            const int o = tid + i * 128;
            cpa16(sA + o * 16, gA + (size_t)o * 4);
        }
#pragma unroll
        for (int i = 0; i < 8; i++) {
            const int o = tid + i * 128;
            cpa16(sB + o * 16, gB + (size_t)o * 4);
        }
        CPA_COMMIT();
    };

    issue(0, 0);
    issue(1, 1);

    for (int c = 0; c < NCH2; ++c) {
        if (c < NCH2 - 1) { CPA_WAIT(1); }
        else              { CPA_WAIT(0); }
        __syncthreads();

        const uint32_t* uA = us + (c % 3) * OSTG;
        const uint32_t* uB = uA + 4096;
#pragma unroll
        for (int ks = 0; ks < 4; ks++) {
            uint4 a[4];
            uint32_t b[8][2];
#pragma unroll
            for (int mt = 0; mt < 4; mt++)
                a[mt] = *(const uint4*)&uA[(((wm * 4 + mt) * 4 + ks) * 32 + lid) * 4];
#pragma unroll
            for (int nt = 0; nt < 8; nt++) {
                const int gn = wn * 8 + nt;          // 8-col group 0..15
                *(uint2*)b[nt] = *(const uint2*)&uB[(gn * 4 + ks) * 64 + lid * 2];
            }
#pragma unroll
            for (int mt = 0; mt < 4; mt++)
#pragma unroll
                for (int nt = 0; nt < 8; nt++)
                    mma_f16(acc[mt][nt], (const uint32_t*)&a[mt], b[nt]);
        }

        if (c + 2 < NCH2) issue(c + 2, (c + 2) % 3);
    }

    const int lr  = lid >> 2;
    const int lc2 = (lid & 3) * 2;
    const int m0  = mb * 128;
    const int n0  = nb * 128;
#pragma unroll
    for (int mt = 0; mt < 4; mt++) {
        const int m = m0 + wm * 64 + mt * 16 + lr;
#pragma unroll
        for (int nt = 0; nt < 8; nt++) {
            const int cg = n0 + wn * 64 + nt * 8 + lc2;
            float* dst = C + (size_t)m * DMODEL + cg;
            *(float2*)dst                         = make_float2(acc[mt][nt][0], acc[mt][nt][1]);
            *(float2*)(dst + (size_t)8 * DMODEL)  = make_float2(acc[mt][nt][2], acc[mt][nt][3]);
        }
    }
}

// ---------------------------------------------------------------------------
// Flash attention v6 (round-11): 128 threads, 64-row Q tiles, Q in regs,
// 3-stage cp.async KV ring, ONE barrier per iteration.
// Epilogue writes out-proj A-fragments (g_of) directly.
// ---------------------------------------------------------------------------
#define KV_U32   4096
#define ATT_SMEM ((3 * 2 * KV_U32 + 4 * 576) * 4)  // 107520 bytes

__global__ void __launch_bounds__(128)
flash_attn_v6()
{
    extern __shared__ uint32_t sm32[];
    const int tid = threadIdx.x;
    const int wid = tid >> 5;
    const int lid = tid & 31;
    const int qb  = gridDim.x - 1 - blockIdx.x;
    const int bh  = blockIdx.y;
    const int b   = bh >> 4;
    const int h   = bh & (NHEADS - 1);
    uint32_t* Pw = sm32 + 3 * 2 * KV_U32 + wid * 576;
    const uint32_t sb = smem_u32(sm32);

    uint32_t q[8][4];
    {
        const uint4* qg = (const uint4*)(g_Qf + (size_t)(bh * 32 + qb) * 4096);
#pragma unroll
        for (int kt = 0; kt < 8; kt++) {
            uint4 v = __ldg(&qg[(kt * 4 + wid) * 32 + lid]);
            q[kt][0] = v.x; q[kt][1] = v.y; q[kt][2] = v.z; q[kt][3] = v.w;
        }
    }

    auto issueKV = [&](int kb, int st) {
        const uint4* gk = (const uint4*)(g_Kf + (size_t)(bh * 32 + kb) * KV_U32);
        const uint4* gv = (const uint4*)(g_Vf + (size_t)(bh * 32 + kb) * KV_U32);
        const uint32_t base = sb + st * (2 * KV_U32 * 4);
#pragma unroll
        for (int i = 0; i < 8; i++)
            cpa16(base + (tid + i * 128) * 16, gk + tid + i * 128);
#pragma unroll
        for (int i = 0; i < 8; i++)
            cpa16(base + KV_U32 * 4 + (tid + i * 128) * 16, gv + tid + i * 128);
        CPA_COMMIT();
    };

    float o[16][4];
#pragma unroll
    for (int nt = 0; nt < 16; nt++)
#pragma unroll
        for (int v = 0; v < 4; v++) o[nt][v] = 0.0f;

    float mx0 = -1e30f, mx1 = -1e30f, l0 = 0.0f, l1 = 0.0f;
    const float scale = 0.08838834764831845f;
    const int lr = lid >> 2;
    const int lc = lid & 3;
    const int q0 = qb * 64;
    const int row0 = q0 + wid * 16 + lr;
    const int row1 = row0 + 8;

    issueKV(0, 0);
    if (qb >= 1) issueKV(1, 1);

    for (int kb = 0; kb <= qb; kb++) {
        if (kb < qb) { CPA_WAIT(1); }
        else         { CPA_WAIT(0); }
        __syncthreads();

        const uint32_t* KB = sm32 + (kb % 3) * 2 * KV_U32;
        const uint32_t* VB = KB + KV_U32;

        float s[8][4];
#pragma unroll
        for (int nt = 0; nt < 8; nt++)
#pragma unroll
            for (int v = 0; v < 4; v++) s[nt][v] = 0.0f;

#pragma unroll
        for (int kt = 0; kt < 8; kt++)
#pragma unroll
            for (int nt = 0; nt < 8; nt++) {
                uint32_t bf[2];
                *(uint2*)bf = *(const uint2*)&KB[(kt * 8 + nt) * 64 + lid * 2];
                mma_f16(s[nt], q[kt], bf);
            }

        const bool domask = (kb == qb);
        const int k0 = kb * 64;
        float ml0 = -1e30f, ml1 = -1e30f;
#pragma unroll
        for (int nt = 0; nt < 8; nt++) {
            const int c0 = k0 + nt * 8 + lc * 2;
            s[nt][0] *= scale; s[nt][1] *= scale;
            s[nt][2] *= scale; s[nt][3] *= scale;
            if (domask) {
                if (c0     > row0) s[nt][0] = -1e30f;
                if (c0 + 1 > row0) s[nt][1] = -1e30f;
                if (c0     > row1) s[nt][2] = -1e30f;
                if (c0 + 1 > row1) s[nt][3] = -1e30f;
            }
            ml0 = fmaxf(ml0, fmaxf(s[nt][0], s[nt][1]));
            ml1 = fmaxf(ml1, fmaxf(s[nt][2], s[nt][3]));
        }
        ml0 = fmaxf(ml0, __shfl_xor_sync(0xffffffffu, ml0, 1));
        ml0 = fmaxf(ml0, __shfl_xor_sync(0xffffffffu, ml0, 2));
        ml1 = fmaxf(ml1, __shfl_xor_sync(0xffffffffu, ml1, 1));
        ml1 = fmaxf(ml1, __shfl_xor_sync(0xffffffffu, ml1, 2));

        const float mn0 = fmaxf(mx0, ml0);
        const float mn1 = fmaxf(mx1, ml1);
        const float f0 = __expf(mx0 - mn0);
        const float f1 = __expf(mx1 - mn1);
        mx0 = mn0; mx1 = mn1;

        float rs0 = 0.0f, rs1 = 0.0f;
#pragma unroll
        for (int nt = 0; nt < 8; nt++) {
            s[nt][0] = __expf(s[nt][0] - mn0);
            s[nt][1] = __expf(s[nt][1] - mn0);
            s[nt][2] = __expf(s[nt][2] - mn1);
            s[nt][3] = __expf(s[nt][3] - mn1);
            rs0 += s[nt][0] + s[nt][1];
            rs1 += s[nt][2] + s[nt][3];
        }
        rs0 += __shfl_xor_sync(0xffffffffu, rs0, 1);
        rs0 += __shfl_xor_sync(0xffffffffu, rs0, 2);
        rs1 += __shfl_xor_sync(0xffffffffu, rs1, 1);
        rs1 += __shfl_xor_sync(0xffffffffu, rs1, 2);
        l0 = l0 * f0 + rs0;
        l1 = l1 * f1 + rs1;

#pragma unroll
        for (int nt = 0; nt < 16; nt++) {
            o[nt][0] *= f0; o[nt][1] *= f0;
            o[nt][2] *= f1; o[nt][3] *= f1;
        }

#pragma unroll
        for (int nt = 0; nt < 8; nt++) {
            Pw[lr * 36 + nt * 4 + lc]       = pack_h2(s[nt][0], s[nt][1]);
            Pw[(lr + 8) * 36 + nt * 4 + lc] = pack_h2(s[nt][2], s[nt][3]);
        }
        __syncwarp();

#pragma unroll
        for (int ks2 = 0; ks2 < 4; ks2++) {
            uint32_t a[4];
            a[0] = Pw[lr * 36 + ks2 * 8 + lc];
            a[1] = Pw[(lr + 8) * 36 + ks2 * 8 + lc];
            a[2] = Pw[lr * 36 + ks2 * 8 + lc + 4];
            a[3] = Pw[(lr + 8) * 36 + ks2 * 8 + lc + 4];
#pragma unroll
            for (int nt = 0; nt < 16; nt++) {
                uint32_t bf[2];
                *(uint2*)bf = *(const uint2*)&VB[(nt * 4 + ks2) * 64 + lid * 2];
                mma_f16(o[nt], a, bf);
            }
        }

        if (kb + 2 <= qb) issueKV(kb + 2, (kb + 2) % 3);
    }

    const float inv0 = 1.0f / l0;
    const float inv1 = 1.0f / l1;
    const int mbp = b * 16 + (qb >> 1);
    const int gm  = (qb & 1) * 4 + wid;
#pragma unroll
    for (int nt = 0; nt < 16; nt++) {
        const int ch   = h * 2 + (nt >> 3);
        const int ks   = (nt & 7) >> 1;
        const int reg0 = (nt & 1) * 2;
        const size_t base = ((size_t)(mbp * NCH2) + ch) * 4096
                          + (gm * 4 + ks) * 128 + (lr * 4 + lc) * 4 + reg0;
        *(uint2*)&g_of[base] = make_uint2(
            pack_h2(o[nt][0] * inv0, o[nt][1] * inv0),
            pack_h2(o[nt][2] * inv1, o[nt][3] * inv1));
    }
}

// ---------------------------------------------------------------------------
// Launch
// ---------------------------------------------------------------------------
extern "C" void kernel_launch(void* const* d_in, const int* in_sizes, int n_in,
                              void* d_out, int out_size)
{
    const float* x    = (const float*)d_in[0];
    const float* Wqkv = (const float*)d_in[1];
    const float* Wout = (const float*)d_in[2];
    float* out = (float*)d_out;

    cudaFuncSetAttribute((const void*)gemm_qkv,
                         cudaFuncAttributeMaxDynamicSharedMemorySize, QKV_SMEM);
    cudaFuncSetAttribute((const void*)gemm_out,
                         cudaFuncAttributeMaxDynamicSharedMemorySize, OUT_SMEM);
    cudaFuncSetAttribute((const void*)flash_attn_v6,
                         cudaFuncAttributeMaxDynamicSharedMemorySize, ATT_SMEM);

    uint32_t *xf, *of, *wqf, *wof;
    cudaGetSymbolAddress((void**)&xf,  g_xf);
    cudaGetSymbolAddress((void**)&of,  g_of);
    cudaGetSymbolAddress((void**)&wqf, g_wqf);
    cudaGetSymbolAddress((void**)&wof, g_wof);

    // Stage 0: all operand conversions in one launch
    conv_all<<<3072, 256>>>(x, Wqkv, Wout);

    // Stage 1: QKV projection (128x96 tiles, 2 CTAs/SM)
    gemm_qkv<<<dim3(64, 32), 128, QKV_SMEM>>>(xf, wqf);

    // Stage 2: flash attention (3-stage ring, 1 barrier/iter)
    flash_attn_v6<<<dim3(32, BATCH * NHEADS), 128, ATT_SMEM>>>();

    // Stage 3: output projection (128x128 tiles, 2 CTAs/SM)
    gemm_out<<<dim3(16, 32), 128, OUT_SMEM>>>(of, wof, out);
}